// round 2
// baseline (speedup 1.0000x reference)
#include <cuda_runtime.h>
#include <cuda_bf16.h>
#include <cstdint>
#include <cstdio>

// ---------------------------------------------------------------------------
// Problem constants
// ---------------------------------------------------------------------------
#define BATCH 8

// Level sizes
#define V1 49152
#define V2 12288
#define V3 3072
#define E1 393216
#define E2 98304
#define E3 24576

// Scratch (device globals; allocation-free rule)
__device__ float g_cheb[125829120];   // 10 * 49152 * 256 floats (max stacked Chebyshev states)
__device__ float g_out[12582912];     // max conv output: 49152*8*32
__device__ int   g_rowPtr[V1 + 1];
__device__ int   g_cursor[V1 + 1];
__device__ int   g_colS[E1];
__device__ float g_valS[E1];
__device__ int   g_orig[E1];
__device__ int   g_bsum[64];

// ---------------------------------------------------------------------------
// Small utility kernels
// ---------------------------------------------------------------------------
__global__ void k_zero_int(int* p, int n) {
    int i = blockIdx.x * blockDim.x + threadIdx.x;
    if (i < n) p[i] = 0;
}

__global__ void k_copy_int(const int* __restrict__ a, int* __restrict__ b, int n) {
    int i = blockIdx.x * blockDim.x + threadIdx.x;
    if (i < n) b[i] = a[i];
}

__global__ void k_copy_f4(const float4* __restrict__ a, float4* __restrict__ b, int n4) {
    int i = blockIdx.x * blockDim.x + threadIdx.x;
    if (i < n4) b[i] = a[i];
}

// transpose input x[B,V] -> cheb slot0 [V, B]
__global__ void k_transpose_in(const float* __restrict__ x, float* __restrict__ out, int V) {
    int v = blockIdx.x * blockDim.x + threadIdx.x;
    if (v < V) {
#pragma unroll
        for (int b = 0; b < BATCH; b++)
            out[(size_t)v * BATCH + b] = x[(size_t)b * V + v];
    }
}

// ---------------------------------------------------------------------------
// CSR build (deterministic: stable by original edge index)
// ---------------------------------------------------------------------------
__global__ void k_hist(const int* __restrict__ rows, int* cnt, int E) {
    int e = blockIdx.x * blockDim.x + threadIdx.x;
    if (e < E) atomicAdd(&cnt[rows[e]], 1);
}

__global__ void k_scan_block(const int* __restrict__ cnt, int* __restrict__ outEx,
                             int* __restrict__ bsum, int V) {
    __shared__ int s[1024];
    int tid = threadIdx.x;
    int i = blockIdx.x * 1024 + tid;
    int v = (i < V) ? cnt[i] : 0;
    s[tid] = v;
    __syncthreads();
    for (int off = 1; off < 1024; off <<= 1) {
        int t = 0;
        if (tid >= off) t = s[tid - off];
        __syncthreads();
        s[tid] += t;
        __syncthreads();
    }
    if (i < V) outEx[i] = s[tid] - v;   // exclusive within block
    if (tid == 1023) bsum[blockIdx.x] = s[1023];
}

__global__ void k_scan_top(int* bsum, int nb) {
    if (blockIdx.x == 0 && threadIdx.x == 0) {
        int acc = 0;
        for (int i = 0; i < nb; i++) { int t = bsum[i]; bsum[i] = acc; acc += t; }
    }
}

__global__ void k_scan_add(int* rowPtr, const int* __restrict__ bsum, int V, int E) {
    int i = blockIdx.x * blockDim.x + threadIdx.x;
    if (i < V) rowPtr[i] += bsum[i >> 10];
    if (i == 0) rowPtr[V] = E;
}

__global__ void k_scatter(const int* __restrict__ rows, const int* __restrict__ cols,
                          const float* __restrict__ vals, int* cursor,
                          int* colS, float* valS, int* orig, int E) {
    int e = blockIdx.x * blockDim.x + threadIdx.x;
    if (e < E) {
        int r = rows[e];
        int pos = atomicAdd(&cursor[r], 1);
        colS[pos] = cols[e];
        valS[pos] = vals[e];
        orig[pos] = e;
    }
}

// per-row insertion sort by original edge index -> fully deterministic CSR
__global__ void k_rowsort(const int* __restrict__ rowPtr, int* colS, float* valS, int* orig, int V) {
    int v = blockIdx.x * blockDim.x + threadIdx.x;
    if (v >= V) return;
    int s = rowPtr[v], e = rowPtr[v + 1];
    for (int i = s + 1; i < e; i++) {
        int ko = orig[i]; int kc = colS[i]; float kv = valS[i];
        int j = i - 1;
        while (j >= s && orig[j] > ko) {
            orig[j + 1] = orig[j]; colS[j + 1] = colS[j]; valS[j + 1] = valS[j];
            j--;
        }
        orig[j + 1] = ko; colS[j + 1] = kc; valS[j + 1] = kv;
    }
}

// ---------------------------------------------------------------------------
// SpMV: y[v,f] = sum_{e in row v} val[e] * x1[col[e], f];   (optionally 2*.. - x0)
// features F = B*C, x layout [V, F] row-major
// ---------------------------------------------------------------------------
__global__ void k_spmv(const int* __restrict__ rowPtr, const int* __restrict__ colS,
                       const float* __restrict__ valS,
                       const float* __restrict__ x1, const float* __restrict__ x0,
                       float* __restrict__ y, int V, int F) {
    int f = blockIdx.x * blockDim.x + threadIdx.x;
    int v = blockIdx.y * blockDim.y + threadIdx.y;
    if (v >= V || f >= F) return;
    int s = rowPtr[v], e = rowPtr[v + 1];
    float acc = 0.f;
    for (int i = s; i < e; i++) {
        acc += valS[i] * x1[(size_t)colS[i] * F + f];
    }
    if (x0) acc = 2.f * acc - x0[(size_t)v * F + f];
    y[(size_t)v * F + f] = acc;
}

// ---------------------------------------------------------------------------
// Chebyshev GEMM:  out[m, n] = ELU( sum_k sum_i cheb[k][m][i] * W[k][i][n] + bias[n] )
// cheb slots strided by M*CIN. M = V*B (divisible by 64).
// ---------------------------------------------------------------------------
__device__ __forceinline__ float elu1(float x) { return x > 0.f ? x : expm1f(x); }

template <int CIN, int COUT>
__global__ void k_cheb_gemm(const float* __restrict__ A, const float* __restrict__ W,
                            const float* __restrict__ bias, float* __restrict__ out, int M) {
    constexpr int BM = 64;
    constexpr int BK = (CIN < 32) ? CIN : 32;
    constexpr int TN = (COUT + 31) / 32;   // 1,2,4
    __shared__ float As[BM][BK + 1];
    __shared__ float Bs[BK][COUT];

    float acc[8][TN];
#pragma unroll
    for (int i = 0; i < 8; i++)
#pragma unroll
        for (int j = 0; j < TN; j++) acc[i][j] = 0.f;

    int tid = threadIdx.x;
    int nIdx = tid & 31;       // n = nIdx + j*32
    int mIdx = tid >> 5;       // m = mBase + mIdx + i*8
    int mBase = blockIdx.x * BM;
    size_t slotStride = (size_t)M * CIN;

    for (int k = 0; k < 10; k++) {
        const float* Ak = A + (size_t)k * slotStride;
        const float* Wk = W + k * CIN * COUT;
        for (int ck = 0; ck < CIN; ck += BK) {
            for (int t = tid; t < BM * BK; t += 256) {
                int r = t / BK, c = t % BK;
                As[r][c] = Ak[(size_t)(mBase + r) * CIN + ck + c];
            }
            for (int t = tid; t < BK * COUT; t += 256) {
                int r = t / COUT, c = t % COUT;
                Bs[r][c] = Wk[(ck + r) * COUT + c];
            }
            __syncthreads();
#pragma unroll
            for (int p = 0; p < BK; p++) {
                float bv[TN];
#pragma unroll
                for (int j = 0; j < TN; j++) bv[j] = Bs[p][nIdx + j * 32];
#pragma unroll
                for (int i = 0; i < 8; i++) {
                    float a = As[mIdx + i * 8][p];
#pragma unroll
                    for (int j = 0; j < TN; j++) acc[i][j] += a * bv[j];
                }
            }
            __syncthreads();
        }
    }

#pragma unroll
    for (int i = 0; i < 8; i++) {
        int m = mBase + mIdx + i * 8;
#pragma unroll
        for (int j = 0; j < TN; j++) {
            int n = nIdx + j * 32;
            float v = acc[i][j] + bias[n];
            out[(size_t)m * COUT + n] = elu1(v);
        }
    }
}

// ---------------------------------------------------------------------------
// Epilogue / pooling kernels
// ---------------------------------------------------------------------------
// skip write: in [V, B*C] -> d_out region [B, V, C]
__global__ void k_skip_write(const float* __restrict__ in, float* __restrict__ out,
                             int V, int C) {
    int t = blockIdx.x * blockDim.x + threadIdx.x;
    int n = V * BATCH * C;
    if (t >= n) return;
    int F = BATCH * C;
    int v = t / F;
    int f = t - v * F;
    int b = f / C;
    int c = f - b * C;
    out[((size_t)b * V + v) * C + c] = in[t];
}

// pool to next level input (vertex-major): out[v', f] = mean_j in[4v'+j, f]
__global__ void k_pool_next(const float* __restrict__ in, float* __restrict__ out,
                            int Vin, int F) {
    int t = blockIdx.x * blockDim.x + threadIdx.x;
    int n = (Vin / 4) * F;
    if (t >= n) return;
    int v4 = t / F;
    int f = t - v4 * F;
    const float* base = in + (size_t)(4 * v4) * F + f;
    out[t] = 0.25f * (base[0] + base[F] + base[2 * F] + base[3 * F]);
}

// pool + transpose write to d_out: [B, Vin/4, C]
__global__ void k_pool_out(const float* __restrict__ in, float* __restrict__ out,
                           int Vin, int C) {
    int t = blockIdx.x * blockDim.x + threadIdx.x;
    int F = BATCH * C;
    int Vout = Vin / 4;
    int n = Vout * F;
    if (t >= n) return;
    int v4 = t / F;
    int f = t - v4 * F;
    int b = f / C;
    int c = f - b * C;
    const float* base = in + (size_t)(4 * v4) * F + f;
    float val = 0.25f * (base[0] + base[F] + base[2 * F] + base[3 * F]);
    out[((size_t)b * Vout + v4) * C + c] = val;
}

// ---------------------------------------------------------------------------
// Host orchestration
// ---------------------------------------------------------------------------
static inline int divUp(int a, int b) { return (a + b - 1) / b; }

struct DevPtrs {
    float* cheb; float* out;
    int* rowPtr; int* cursor; int* colS; float* valS; int* orig; int* bsum;
};

static void get_ptrs(DevPtrs& p) {
    cudaGetSymbolAddress((void**)&p.cheb, g_cheb);
    cudaGetSymbolAddress((void**)&p.out, g_out);
    cudaGetSymbolAddress((void**)&p.rowPtr, g_rowPtr);
    cudaGetSymbolAddress((void**)&p.cursor, g_cursor);
    cudaGetSymbolAddress((void**)&p.colS, g_colS);
    cudaGetSymbolAddress((void**)&p.valS, g_valS);
    cudaGetSymbolAddress((void**)&p.orig, g_orig);
    cudaGetSymbolAddress((void**)&p.bsum, g_bsum);
}

static void build_csr(const DevPtrs& p, const int* rows, const int* cols, const float* vals,
                      int V, int E) {
    k_zero_int<<<divUp(V + 1, 256), 256>>>(p.cursor, V + 1);
    k_hist<<<divUp(E, 256), 256>>>(rows, p.cursor, E);
    int nb = divUp(V, 1024);
    k_scan_block<<<nb, 1024>>>(p.cursor, p.rowPtr, p.bsum, V);
    k_scan_top<<<1, 32>>>(p.bsum, nb);
    k_scan_add<<<divUp(V + 1, 256), 256>>>(p.rowPtr, p.bsum, V, E);
    k_copy_int<<<divUp(V, 256), 256>>>(p.rowPtr, p.cursor, V);
    k_scatter<<<divUp(E, 256), 256>>>(rows, cols, vals, p.cursor, p.colS, p.valS, p.orig, E);
    k_rowsort<<<divUp(V, 128), 128>>>(p.rowPtr, p.colS, p.valS, p.orig, V);
}

static void spmv_chain(const DevPtrs& p, int V, int F) {
    size_t S = (size_t)V * F;
    dim3 blk = (F >= 32) ? dim3(32, 8) : dim3(8, 32);
    dim3 grd = (F >= 32) ? dim3(F / 32, V / 8) : dim3(1, V / 32);
    // x1 = L x0
    k_spmv<<<grd, blk>>>(p.rowPtr, p.colS, p.valS, p.cheb, nullptr, p.cheb + S, V, F);
    for (int k = 2; k < 10; k++) {
        k_spmv<<<grd, blk>>>(p.rowPtr, p.colS, p.valS,
                             p.cheb + (size_t)(k - 1) * S, p.cheb + (size_t)(k - 2) * S,
                             p.cheb + (size_t)k * S, V, F);
    }
}

template <int CIN, int COUT>
static void run_gemm(const DevPtrs& p, int V, const float* w, const float* b) {
    int M = V * BATCH;
    k_cheb_gemm<CIN, COUT><<<M / 64, 256>>>(p.cheb, w, b, p.out, M);
}

extern "C" void kernel_launch(void* const* d_in, const int* in_sizes, int n_in,
                              void* d_out_v, int out_size) {
    (void)in_sizes; (void)n_in; (void)out_size;
    DevPtrs p; get_ptrs(p);

    const float* x    = (const float*)d_in[0];
    const float* w1_1 = (const float*)d_in[1];
    const float* b1_1 = (const float*)d_in[2];
    const float* w2_1 = (const float*)d_in[3];
    const float* b2_1 = (const float*)d_in[4];
    const int*   rows1 = (const int*)d_in[5];
    const int*   cols1 = (const int*)d_in[6];
    const float* vals1 = (const float*)d_in[7];
    const float* w1_2 = (const float*)d_in[8];
    const float* b1_2 = (const float*)d_in[9];
    const float* w2_2 = (const float*)d_in[10];
    const float* b2_2 = (const float*)d_in[11];
    const int*   rows2 = (const int*)d_in[12];
    const int*   cols2 = (const int*)d_in[13];
    const float* vals2 = (const float*)d_in[14];
    const float* w1_3 = (const float*)d_in[15];
    const float* b1_3 = (const float*)d_in[16];
    const float* w2_3 = (const float*)d_in[17];
    const float* b2_3 = (const float*)d_in[18];
    const int*   rows3 = (const int*)d_in[19];
    const int*   cols3 = (const int*)d_in[20];
    const float* vals3 = (const float*)d_in[21];

    float* d_out = (float*)d_out_v;
    float* out_skip1 = d_out;                                    // [8,49152,32]
    float* out_skip2 = d_out + (size_t)12582912;                 // [8,12288,64]
    float* out_skip3 = out_skip2 + (size_t)6291456;              // [8,3072,128]
    float* out_x     = out_skip3 + (size_t)3145728;              // [8,768,128]

    // ---------------- Level 1 ----------------
    build_csr(p, rows1, cols1, vals1, V1, E1);
    k_transpose_in<<<divUp(V1, 256), 256>>>(x, p.cheb, V1);
    spmv_chain(p, V1, BATCH * 1);
    run_gemm<1, 32>(p, V1, w1_1, b1_1);

    {   // copy conv1 output -> cheb slot 0
        int n = V1 * BATCH * 32;
        k_copy_f4<<<divUp(n / 4, 256), 256>>>((const float4*)p.out, (float4*)p.cheb, n / 4);
    }
    spmv_chain(p, V1, BATCH * 32);
    run_gemm<32, 32>(p, V1, w2_1, b2_1);
    {
        int n = V1 * BATCH * 32;
        k_skip_write<<<divUp(n, 256), 256>>>(p.out, out_skip1, V1, 32);
        int n2 = (V1 / 4) * BATCH * 32;
        k_pool_next<<<divUp(n2, 256), 256>>>(p.out, p.cheb, V1, BATCH * 32);
    }

    // ---------------- Level 2 ----------------
    build_csr(p, rows2, cols2, vals2, V2, E2);
    spmv_chain(p, V2, BATCH * 32);
    run_gemm<32, 64>(p, V2, w1_2, b1_2);
    {
        int n = V2 * BATCH * 64;
        k_copy_f4<<<divUp(n / 4, 256), 256>>>((const float4*)p.out, (float4*)p.cheb, n / 4);
    }
    spmv_chain(p, V2, BATCH * 64);
    run_gemm<64, 64>(p, V2, w2_2, b2_2);
    {
        int n = V2 * BATCH * 64;
        k_skip_write<<<divUp(n, 256), 256>>>(p.out, out_skip2, V2, 64);
        int n2 = (V2 / 4) * BATCH * 64;
        k_pool_next<<<divUp(n2, 256), 256>>>(p.out, p.cheb, V2, BATCH * 64);
    }

    // ---------------- Level 3 ----------------
    build_csr(p, rows3, cols3, vals3, V3, E3);
    spmv_chain(p, V3, BATCH * 64);
    run_gemm<64, 128>(p, V3, w1_3, b1_3);
    {
        int n = V3 * BATCH * 128;
        k_copy_f4<<<divUp(n / 4, 256), 256>>>((const float4*)p.out, (float4*)p.cheb, n / 4);
    }
    spmv_chain(p, V3, BATCH * 128);
    run_gemm<128, 128>(p, V3, w2_3, b2_3);
    {
        int n = V3 * BATCH * 128;
        k_skip_write<<<divUp(n, 256), 256>>>(p.out, out_skip3, V3, 128);
        int n2 = (V3 / 4) * BATCH * 128;
        k_pool_out<<<divUp(n2, 256), 256>>>(p.out, out_x, V3, 128);
    }
}

// round 3
// speedup vs baseline: 2.5481x; 2.5481x over previous
#include <cuda_runtime.h>
#include <cuda_bf16.h>
#include <cstdint>
#include <cstdio>

#define BATCH 8
#define V1 49152
#define V2 12288
#define V3 3072
#define E1 393216
#define E2 98304
#define E3 24576

// Scratch (device globals; allocation-free rule)
__device__ float g_cheb[125829120];   // 10 * 49152 * 256 floats
__device__ float g_out[12582912];     // conv1 outputs (max 49152*8*32)
__device__ float g_out2[12582912];    // conv2 outputs
__device__ int   g_rowPtr[V1 + 1];
__device__ int   g_cursor[V1 + 1];
__device__ int   g_colS[E1];
__device__ float g_valS[E1];
__device__ int   g_orig[E1];
__device__ int   g_bsum[64];

__device__ __forceinline__ float elu1(float x) { return x > 0.f ? x : expm1f(x); }

// ---------------------------------------------------------------------------
// Utility kernels
// ---------------------------------------------------------------------------
__global__ void k_zero_int(int* p, int n) {
    int i = blockIdx.x * blockDim.x + threadIdx.x;
    if (i < n) p[i] = 0;
}
__global__ void k_copy_int(const int* __restrict__ a, int* __restrict__ b, int n) {
    int i = blockIdx.x * blockDim.x + threadIdx.x;
    if (i < n) b[i] = a[i];
}
// transpose x[B,V] -> [V,B]
__global__ void k_transpose_in(const float* __restrict__ x, float* __restrict__ out, int V) {
    int v = blockIdx.x * blockDim.x + threadIdx.x;
    if (v < V) {
#pragma unroll
        for (int b = 0; b < BATCH; b++)
            out[(size_t)v * BATCH + b] = x[(size_t)b * V + v];
    }
}

// ---------------------------------------------------------------------------
// CSR build (deterministic via stable per-row sort by original edge index)
// ---------------------------------------------------------------------------
__global__ void k_hist(const int* __restrict__ rows, int* cnt, int E) {
    int e = blockIdx.x * blockDim.x + threadIdx.x;
    if (e < E) atomicAdd(&cnt[rows[e]], 1);
}
__global__ void k_scan_block(const int* __restrict__ cnt, int* __restrict__ outEx,
                             int* __restrict__ bsum, int V) {
    __shared__ int s[1024];
    int tid = threadIdx.x;
    int i = blockIdx.x * 1024 + tid;
    int v = (i < V) ? cnt[i] : 0;
    s[tid] = v;
    __syncthreads();
    for (int off = 1; off < 1024; off <<= 1) {
        int t = 0;
        if (tid >= off) t = s[tid - off];
        __syncthreads();
        s[tid] += t;
        __syncthreads();
    }
    if (i < V) outEx[i] = s[tid] - v;
    if (tid == 1023) bsum[blockIdx.x] = s[1023];
}
__global__ void k_scan_top(int* bsum, int nb) {
    __shared__ int s[64];
    int t = threadIdx.x;
    int v = (t < nb) ? bsum[t] : 0;
    s[t] = v;
    __syncthreads();
    for (int off = 1; off < 64; off <<= 1) {
        int x = (t >= off) ? s[t - off] : 0;
        __syncthreads();
        s[t] += x;
        __syncthreads();
    }
    if (t < nb) bsum[t] = s[t] - v;   // exclusive
}
__global__ void k_scan_add(int* rowPtr, const int* __restrict__ bsum, int V, int E) {
    int i = blockIdx.x * blockDim.x + threadIdx.x;
    if (i < V) rowPtr[i] += bsum[i >> 10];
    if (i == 0) rowPtr[V] = E;
}
__global__ void k_scatter(const int* __restrict__ rows, const int* __restrict__ cols,
                          const float* __restrict__ vals, int* cursor,
                          int* colS, float* valS, int* orig, int E) {
    int e = blockIdx.x * blockDim.x + threadIdx.x;
    if (e < E) {
        int r = rows[e];
        int pos = atomicAdd(&cursor[r], 1);
        colS[pos] = cols[e];
        valS[pos] = vals[e];
        orig[pos] = e;
    }
}
__global__ void k_rowsort(const int* __restrict__ rowPtr, int* colS, float* valS, int* orig, int V) {
    int v = blockIdx.x * blockDim.x + threadIdx.x;
    if (v >= V) return;
    int s = rowPtr[v], e = rowPtr[v + 1];
    for (int i = s + 1; i < e; i++) {
        int ko = orig[i]; int kc = colS[i]; float kv = valS[i];
        int j = i - 1;
        while (j >= s && orig[j] > ko) {
            orig[j + 1] = orig[j]; colS[j + 1] = colS[j]; valS[j + 1] = valS[j];
            j--;
        }
        orig[j + 1] = ko; colS[j + 1] = kc; valS[j + 1] = kv;
    }
}

// ---------------------------------------------------------------------------
// SpMV (float4, 2-edge unrolled):  y = L*xin   or   y = 2*L*xin - xprev
// ---------------------------------------------------------------------------
template <int F4, int ROWS>
__global__ void k_spmv4(const int* __restrict__ rowPtr, const int* __restrict__ colS,
                        const float* __restrict__ valS,
                        const float4* __restrict__ xin, const float4* __restrict__ xprev,
                        float4* __restrict__ y, int V) {
    int f = threadIdx.x;
    int v = blockIdx.x * ROWS + threadIdx.y;
    int s = rowPtr[v], e = rowPtr[v + 1];
    float4 acc = make_float4(0.f, 0.f, 0.f, 0.f);
    int i = s;
    for (; i + 2 <= e; i += 2) {
        int c0 = colS[i];     float w0 = valS[i];
        int c1 = colS[i + 1]; float w1 = valS[i + 1];
        float4 g0 = xin[(size_t)c0 * F4 + f];
        float4 g1 = xin[(size_t)c1 * F4 + f];
        acc.x += w0 * g0.x; acc.y += w0 * g0.y; acc.z += w0 * g0.z; acc.w += w0 * g0.w;
        acc.x += w1 * g1.x; acc.y += w1 * g1.y; acc.z += w1 * g1.z; acc.w += w1 * g1.w;
    }
    if (i < e) {
        int c0 = colS[i]; float w0 = valS[i];
        float4 g0 = xin[(size_t)c0 * F4 + f];
        acc.x += w0 * g0.x; acc.y += w0 * g0.y; acc.z += w0 * g0.z; acc.w += w0 * g0.w;
    }
    if (xprev) {
        float4 pv = xprev[(size_t)v * F4 + f];
        acc.x = 2.f * acc.x - pv.x; acc.y = 2.f * acc.y - pv.y;
        acc.z = 2.f * acc.z - pv.z; acc.w = 2.f * acc.w - pv.w;
    }
    y[(size_t)v * F4 + f] = acc;
}

// ---------------------------------------------------------------------------
// Register-tiled Chebyshev GEMM.
// A = 10 stacked slots: slot0 = A0, slot k>=1 = Arest + (k-1)*slotStride.
// out[m,n] = ELU( sum_k sum_i A_k[m,i] * W[k,i,n] + bias[n] )
// ---------------------------------------------------------------------------
template <int CIN, int COUT, int BM, int BK, int TM, int TN>
__global__ void k_gemm(const float* __restrict__ A0, const float* __restrict__ Arest,
                       size_t slotStride, const float* __restrict__ W,
                       const float* __restrict__ bias, float* __restrict__ out) {
    constexpr int THREADS = (BM / TM) * (COUT / TN);
    static_assert(THREADS == 256, "thread count");
    constexpr int MC = TM / 4;
    constexpr int NC = TN / 4;
    constexpr int MSTRIDE = BM / MC;
    constexpr int NSTRIDE = COUT / NC;
    constexpr int NT = COUT / TN;

    __shared__ float As[BK][BM];
    __shared__ float Bs[BK][COUT];

    int tid = threadIdx.x;
    int nt = tid % NT;
    int mt = tid / NT;
    int mBase = blockIdx.x * BM;

    float acc[TM][TN];
#pragma unroll
    for (int i = 0; i < TM; i++)
#pragma unroll
        for (int j = 0; j < TN; j++) acc[i][j] = 0.f;

    for (int k = 0; k < 10; k++) {
        const float* Ak = (k == 0) ? A0 : (Arest + (size_t)(k - 1) * slotStride);
        const float* Wk = W + k * CIN * COUT;
#pragma unroll 1
        for (int ck = 0; ck < CIN; ck += BK) {
            // A tile -> transposed smem
#pragma unroll
            for (int idx = tid; idx < BM * BK / 4; idx += THREADS) {
                int r = idx / (BK / 4);
                int c4 = idx % (BK / 4);
                float4 a = *(const float4*)&Ak[(size_t)(mBase + r) * CIN + ck + c4 * 4];
                As[c4 * 4 + 0][r] = a.x;
                As[c4 * 4 + 1][r] = a.y;
                As[c4 * 4 + 2][r] = a.z;
                As[c4 * 4 + 3][r] = a.w;
            }
            // B tile
#pragma unroll
            for (int idx = tid; idx < BK * COUT / 4; idx += THREADS) {
                int r = idx / (COUT / 4);
                int c4 = idx % (COUT / 4);
                *(float4*)&Bs[r][c4 * 4] = *(const float4*)&Wk[(ck + r) * COUT + c4 * 4];
            }
            __syncthreads();
#pragma unroll
            for (int p = 0; p < BK; p++) {
                float af[TM], bf[TN];
#pragma unroll
                for (int j = 0; j < MC; j++) {
                    float4 a4 = *(const float4*)&As[p][j * MSTRIDE + mt * 4];
                    af[j * 4 + 0] = a4.x; af[j * 4 + 1] = a4.y;
                    af[j * 4 + 2] = a4.z; af[j * 4 + 3] = a4.w;
                }
#pragma unroll
                for (int j = 0; j < NC; j++) {
                    float4 b4 = *(const float4*)&Bs[p][j * NSTRIDE + nt * 4];
                    bf[j * 4 + 0] = b4.x; bf[j * 4 + 1] = b4.y;
                    bf[j * 4 + 2] = b4.z; bf[j * 4 + 3] = b4.w;
                }
#pragma unroll
                for (int i = 0; i < TM; i++)
#pragma unroll
                    for (int j = 0; j < TN; j++) acc[i][j] += af[i] * bf[j];
            }
            __syncthreads();
        }
    }

    // epilogue: bias + ELU, float4 stores
#pragma unroll
    for (int jm = 0; jm < MC; jm++) {
#pragma unroll
        for (int ii = 0; ii < 4; ii++) {
            int m = mBase + jm * MSTRIDE + mt * 4 + ii;
#pragma unroll
            for (int jn = 0; jn < NC; jn++) {
                int n0 = jn * NSTRIDE + nt * 4;
                float4 o;
                o.x = elu1(acc[jm * 4 + ii][jn * 4 + 0] + bias[n0 + 0]);
                o.y = elu1(acc[jm * 4 + ii][jn * 4 + 1] + bias[n0 + 1]);
                o.z = elu1(acc[jm * 4 + ii][jn * 4 + 2] + bias[n0 + 2]);
                o.w = elu1(acc[jm * 4 + ii][jn * 4 + 3] + bias[n0 + 3]);
                *(float4*)&out[(size_t)m * COUT + n0] = o;
            }
        }
    }
}

// CIN=1 special case (level-1 conv1): out[m,n] = ELU( sum_k A_k[m] * W[k,0,n] + b[n] )
__global__ void k_gemm_c1(const float* __restrict__ A0, const float* __restrict__ Arest,
                          size_t slotStride, const float* __restrict__ W,
                          const float* __restrict__ bias, float* __restrict__ out, int M) {
    __shared__ float Ws[10][32];
    __shared__ float bs[32];
    int tid = threadIdx.y * 32 + threadIdx.x;
    for (int t = tid; t < 320; t += 256) Ws[t / 32][t % 32] = W[t];
    if (tid < 32) bs[tid] = bias[tid];
    __syncthreads();
    int m = blockIdx.x * 8 + threadIdx.y;
    int n = threadIdx.x;
    float acc = 0.f;
    acc += A0[m] * Ws[0][n];
#pragma unroll
    for (int k = 1; k < 10; k++)
        acc += Arest[(size_t)(k - 1) * slotStride + m] * Ws[k][n];
    out[(size_t)m * 32 + n] = elu1(acc + bs[n]);
}

// ---------------------------------------------------------------------------
// Epilogue / pooling kernels (float4)
// ---------------------------------------------------------------------------
// in [V, B*C] -> out [B, V, C]
__global__ void k_skip4(const float4* __restrict__ in, float4* __restrict__ out,
                        int V, int C4) {
    int t = blockIdx.x * blockDim.x + threadIdx.x;
    int F4 = BATCH * C4;
    int n = V * F4;
    if (t >= n) return;
    int v = t / F4;
    int f = t - v * F4;
    int b = f / C4;
    int c = f - b * C4;
    out[((size_t)b * V + v) * C4 + c] = in[t];
}
// pool to next level input (vertex-major)
__global__ void k_pool_next4(const float4* __restrict__ in, float4* __restrict__ out,
                             int Vin, int F4) {
    int t = blockIdx.x * blockDim.x + threadIdx.x;
    int n = (Vin / 4) * F4;
    if (t >= n) return;
    int v4 = t / F4;
    int f = t - v4 * F4;
    const float4* base = in + (size_t)(4 * v4) * F4 + f;
    float4 a = base[0], b = base[F4], c = base[2 * F4], d = base[3 * F4];
    float4 o;
    o.x = 0.25f * (a.x + b.x + c.x + d.x);
    o.y = 0.25f * (a.y + b.y + c.y + d.y);
    o.z = 0.25f * (a.z + b.z + c.z + d.z);
    o.w = 0.25f * (a.w + b.w + c.w + d.w);
    out[t] = o;
}
// pool + transpose to d_out [B, Vin/4, C]
__global__ void k_pool_out4(const float4* __restrict__ in, float4* __restrict__ out,
                            int Vin, int C4) {
    int t = blockIdx.x * blockDim.x + threadIdx.x;
    int F4 = BATCH * C4;
    int Vout = Vin / 4;
    int n = Vout * F4;
    if (t >= n) return;
    int v4 = t / F4;
    int f = t - v4 * F4;
    int b = f / C4;
    int c = f - b * C4;
    const float4* base = in + (size_t)(4 * v4) * F4 + f;
    float4 aa = base[0], bb = base[F4], cc = base[2 * F4], dd = base[3 * F4];
    float4 o;
    o.x = 0.25f * (aa.x + bb.x + cc.x + dd.x);
    o.y = 0.25f * (aa.y + bb.y + cc.y + dd.y);
    o.z = 0.25f * (aa.z + bb.z + cc.z + dd.z);
    o.w = 0.25f * (aa.w + bb.w + cc.w + dd.w);
    out[((size_t)b * Vout + v4) * C4 + c] = o;
}

// ---------------------------------------------------------------------------
// Host orchestration
// ---------------------------------------------------------------------------
static inline int divUp(int a, int b) { return (a + b - 1) / b; }

struct DevPtrs {
    float* cheb; float* out; float* out2;
    int* rowPtr; int* cursor; int* colS; float* valS; int* orig; int* bsum;
};
static void get_ptrs(DevPtrs& p) {
    cudaGetSymbolAddress((void**)&p.cheb, g_cheb);
    cudaGetSymbolAddress((void**)&p.out, g_out);
    cudaGetSymbolAddress((void**)&p.out2, g_out2);
    cudaGetSymbolAddress((void**)&p.rowPtr, g_rowPtr);
    cudaGetSymbolAddress((void**)&p.cursor, g_cursor);
    cudaGetSymbolAddress((void**)&p.colS, g_colS);
    cudaGetSymbolAddress((void**)&p.valS, g_valS);
    cudaGetSymbolAddress((void**)&p.orig, g_orig);
    cudaGetSymbolAddress((void**)&p.bsum, g_bsum);
}

static void build_csr(const DevPtrs& p, const int* rows, const int* cols, const float* vals,
                      int V, int E) {
    k_zero_int<<<divUp(V + 1, 256), 256>>>(p.cursor, V + 1);
    k_hist<<<divUp(E, 256), 256>>>(rows, p.cursor, E);
    int nb = divUp(V, 1024);
    k_scan_block<<<nb, 1024>>>(p.cursor, p.rowPtr, p.bsum, V);
    k_scan_top<<<1, 64>>>(p.bsum, nb);
    k_scan_add<<<divUp(V + 1, 256), 256>>>(p.rowPtr, p.bsum, V, E);
    k_copy_int<<<divUp(V, 256), 256>>>(p.rowPtr, p.cursor, V);
    k_scatter<<<divUp(E, 256), 256>>>(rows, cols, vals, p.cursor, p.colS, p.valS, p.orig, E);
    k_rowsort<<<divUp(V, 128), 128>>>(p.rowPtr, p.colS, p.valS, p.orig, V);
}

// Chebyshev chain: slot0 = x0base (external), slots 1..9 at cheb + k*S.
template <int F>
static void spmv_chain(const DevPtrs& p, const float* x0base, int V) {
    constexpr int F4 = F / 4;
    constexpr int ROWS = (F4 >= 256) ? 1 : (256 / F4);
    dim3 blk(F4, ROWS);
    size_t S = (size_t)V * F;
    k_spmv4<F4, ROWS><<<V / ROWS, blk>>>(p.rowPtr, p.colS, p.valS,
                                         (const float4*)x0base, nullptr,
                                         (float4*)(p.cheb + S), V);
    for (int k = 2; k < 10; k++) {
        const float* xk1 = p.cheb + (size_t)(k - 1) * S;
        const float* xk2 = (k == 2) ? x0base : (p.cheb + (size_t)(k - 2) * S);
        k_spmv4<F4, ROWS><<<V / ROWS, blk>>>(p.rowPtr, p.colS, p.valS,
                                             (const float4*)xk1, (const float4*)xk2,
                                             (float4*)(p.cheb + (size_t)k * S), V);
    }
}

extern "C" void kernel_launch(void* const* d_in, const int* in_sizes, int n_in,
                              void* d_out_v, int out_size) {
    (void)in_sizes; (void)n_in; (void)out_size;
    DevPtrs p; get_ptrs(p);

    const float* x    = (const float*)d_in[0];
    const float* w1_1 = (const float*)d_in[1];
    const float* b1_1 = (const float*)d_in[2];
    const float* w2_1 = (const float*)d_in[3];
    const float* b2_1 = (const float*)d_in[4];
    const int*   rows1 = (const int*)d_in[5];
    const int*   cols1 = (const int*)d_in[6];
    const float* vals1 = (const float*)d_in[7];
    const float* w1_2 = (const float*)d_in[8];
    const float* b1_2 = (const float*)d_in[9];
    const float* w2_2 = (const float*)d_in[10];
    const float* b2_2 = (const float*)d_in[11];
    const int*   rows2 = (const int*)d_in[12];
    const int*   cols2 = (const int*)d_in[13];
    const float* vals2 = (const float*)d_in[14];
    const float* w1_3 = (const float*)d_in[15];
    const float* b1_3 = (const float*)d_in[16];
    const float* w2_3 = (const float*)d_in[17];
    const float* b2_3 = (const float*)d_in[18];
    const int*   rows3 = (const int*)d_in[19];
    const int*   cols3 = (const int*)d_in[20];
    const float* vals3 = (const float*)d_in[21];

    float* d_out = (float*)d_out_v;
    float* out_skip1 = d_out;                       // [8,49152,32]
    float* out_skip2 = d_out + (size_t)12582912;    // [8,12288,64]
    float* out_skip3 = out_skip2 + (size_t)6291456; // [8,3072,128]
    float* out_x     = out_skip3 + (size_t)3145728; // [8,768,128]

    // ---------------- Level 1 ----------------
    build_csr(p, rows1, cols1, vals1, V1, E1);
    k_transpose_in<<<divUp(V1, 256), 256>>>(x, p.cheb, V1);
    spmv_chain<8>(p, p.cheb, V1);
    k_gemm_c1<<<V1 * BATCH / 8, dim3(32, 8)>>>(p.cheb, p.cheb + (size_t)V1 * 8,
                                               (size_t)V1 * 8, w1_1, b1_1, p.out, V1 * BATCH);

    spmv_chain<256>(p, p.out, V1);
    k_gemm<32, 32, 128, 32, 4, 4><<<V1 * BATCH / 128, 256>>>(
        p.out, p.cheb + (size_t)V1 * 256, (size_t)V1 * 256, w2_1, b2_1, p.out2);
    {
        int n = V1 * BATCH * 8;  // /4 already (C4=8)
        k_skip4<<<divUp(n, 256), 256>>>((const float4*)p.out2, (float4*)out_skip1, V1, 8);
        int n2 = (V1 / 4) * BATCH * 8;
        k_pool_next4<<<divUp(n2, 256), 256>>>((const float4*)p.out2, (float4*)p.cheb, V1, BATCH * 8);
    }

    // ---------------- Level 2 ----------------
    build_csr(p, rows2, cols2, vals2, V2, E2);
    spmv_chain<256>(p, p.cheb, V2);
    k_gemm<32, 64, 128, 32, 8, 4><<<V2 * BATCH / 128, 256>>>(
        p.cheb, p.cheb + (size_t)V2 * 256, (size_t)V2 * 256, w1_2, b1_2, p.out);

    spmv_chain<512>(p, p.out, V2);
    k_gemm<64, 64, 128, 32, 8, 4><<<V2 * BATCH / 128, 256>>>(
        p.out, p.cheb + (size_t)V2 * 512, (size_t)V2 * 512, w2_2, b2_2, p.out2);
    {
        int n = V2 * BATCH * 16;
        k_skip4<<<divUp(n, 256), 256>>>((const float4*)p.out2, (float4*)out_skip2, V2, 16);
        int n2 = (V2 / 4) * BATCH * 16;
        k_pool_next4<<<divUp(n2, 256), 256>>>((const float4*)p.out2, (float4*)p.cheb, V2, BATCH * 16);
    }

    // ---------------- Level 3 ----------------
    build_csr(p, rows3, cols3, vals3, V3, E3);
    spmv_chain<512>(p, p.cheb, V3);
    k_gemm<64, 128, 128, 16, 8, 8><<<V3 * BATCH / 128, 256>>>(
        p.cheb, p.cheb + (size_t)V3 * 512, (size_t)V3 * 512, w1_3, b1_3, p.out);

    spmv_chain<1024>(p, p.out, V3);
    k_gemm<128, 128, 128, 16, 8, 8><<<V3 * BATCH / 128, 256>>>(
        p.out, p.cheb + (size_t)V3 * 1024, (size_t)V3 * 1024, w2_3, b2_3, p.out2);
    {
        int n = V3 * BATCH * 32;
        k_skip4<<<divUp(n, 256), 256>>>((const float4*)p.out2, (float4*)out_skip3, V3, 32);
        int n2 = (V3 / 4) * BATCH * 32;
        k_pool_out4<<<divUp(n2, 256), 256>>>((const float4*)p.out2, (float4*)out_x, V3, 32);
    }
}

// round 5
// speedup vs baseline: 3.1803x; 1.2481x over previous
#include <cuda_runtime.h>
#include <cuda_bf16.h>
#include <cstdint>
#include <cstdio>

#define BATCH 8
#define V1 49152
#define V2 12288
#define V3 3072
#define E1 393216
#define E2 98304
#define E3 24576

// Scratch (device globals; allocation-free rule)
__device__ float g_cheb[125829120];   // 10 * 49152 * 256 floats
__device__ float g_out[12582912];
__device__ float g_out2[12582912];
__device__ int   g_rowPtr[V1 + 1];
__device__ int   g_cursor[V1 + 1];
__device__ int   g_colS[E1];
__device__ float g_valS[E1];
__device__ int   g_orig[E1];
__device__ int   g_bsum[64];

__device__ __forceinline__ float elu1(float x) { return x > 0.f ? x : expm1f(x); }

// ---------------------------------------------------------------------------
// Utility kernels
// ---------------------------------------------------------------------------
__global__ void k_zero_int(int* p, int n) {
    int i = blockIdx.x * blockDim.x + threadIdx.x;
    if (i < n) p[i] = 0;
}
__global__ void k_copy_int(const int* __restrict__ a, int* __restrict__ b, int n) {
    int i = blockIdx.x * blockDim.x + threadIdx.x;
    if (i < n) b[i] = a[i];
}
__global__ void k_transpose_in(const float* __restrict__ x, float* __restrict__ out, int V) {
    int v = blockIdx.x * blockDim.x + threadIdx.x;
    if (v < V) {
#pragma unroll
        for (int b = 0; b < BATCH; b++)
            out[(size_t)v * BATCH + b] = x[(size_t)b * V + v];
    }
}

// ---------------------------------------------------------------------------
// CSR build (deterministic)
// ---------------------------------------------------------------------------
__global__ void k_hist(const int* __restrict__ rows, int* cnt, int E) {
    int e = blockIdx.x * blockDim.x + threadIdx.x;
    if (e < E) atomicAdd(&cnt[rows[e]], 1);
}
__global__ void k_scan_block(const int* __restrict__ cnt, int* __restrict__ outEx,
                             int* __restrict__ bsum, int V) {
    __shared__ int s[1024];
    int tid = threadIdx.x;
    int i = blockIdx.x * 1024 + tid;
    int v = (i < V) ? cnt[i] : 0;
    s[tid] = v;
    __syncthreads();
    for (int off = 1; off < 1024; off <<= 1) {
        int t = 0;
        if (tid >= off) t = s[tid - off];
        __syncthreads();
        s[tid] += t;
        __syncthreads();
    }
    if (i < V) outEx[i] = s[tid] - v;
    if (tid == 1023) bsum[blockIdx.x] = s[1023];
}
__global__ void k_scan_top(int* bsum, int nb) {
    __shared__ int s[64];
    int t = threadIdx.x;
    int v = (t < nb) ? bsum[t] : 0;
    s[t] = v;
    __syncthreads();
    for (int off = 1; off < 64; off <<= 1) {
        int x = (t >= off) ? s[t - off] : 0;
        __syncthreads();
        s[t] += x;
        __syncthreads();
    }
    if (t < nb) bsum[t] = s[t] - v;
}
__global__ void k_scan_add(int* rowPtr, const int* __restrict__ bsum, int V, int E) {
    int i = blockIdx.x * blockDim.x + threadIdx.x;
    if (i < V) rowPtr[i] += bsum[i >> 10];
    if (i == 0) rowPtr[V] = E;
}
__global__ void k_scatter(const int* __restrict__ rows, const int* __restrict__ cols,
                          const float* __restrict__ vals, int* cursor,
                          int* colS, float* valS, int* orig, int E) {
    int e = blockIdx.x * blockDim.x + threadIdx.x;
    if (e < E) {
        int r = rows[e];
        int pos = atomicAdd(&cursor[r], 1);
        colS[pos] = cols[e];
        valS[pos] = vals[e];
        orig[pos] = e;
    }
}
__global__ void k_rowsort(const int* __restrict__ rowPtr, int* colS, float* valS, int* orig, int V) {
    int v = blockIdx.x * blockDim.x + threadIdx.x;
    if (v >= V) return;
    int s = rowPtr[v], e = rowPtr[v + 1];
    for (int i = s + 1; i < e; i++) {
        int ko = orig[i]; int kc = colS[i]; float kv = valS[i];
        int j = i - 1;
        while (j >= s && orig[j] > ko) {
            orig[j + 1] = orig[j]; colS[j + 1] = colS[j]; valS[j + 1] = valS[j];
            j--;
        }
        orig[j + 1] = ko; colS[j + 1] = kc; valS[j + 1] = kv;
    }
}

// ---------------------------------------------------------------------------
// SpMV (float4, 4-edge unrolled)
// ---------------------------------------------------------------------------
template <int F4, int ROWS>
__global__ void k_spmv4(const int* __restrict__ rowPtr, const int* __restrict__ colS,
                        const float* __restrict__ valS,
                        const float4* __restrict__ xin, const float4* __restrict__ xprev,
                        float4* __restrict__ y, int V) {
    int f = threadIdx.x;
    int v = blockIdx.x * ROWS + threadIdx.y;
    int s = rowPtr[v], e = rowPtr[v + 1];
    float4 acc = make_float4(0.f, 0.f, 0.f, 0.f);
    int i = s;
    for (; i + 4 <= e; i += 4) {
        int c0 = colS[i];     float w0 = valS[i];
        int c1 = colS[i + 1]; float w1 = valS[i + 1];
        int c2 = colS[i + 2]; float w2 = valS[i + 2];
        int c3 = colS[i + 3]; float w3 = valS[i + 3];
        float4 g0 = xin[(size_t)c0 * F4 + f];
        float4 g1 = xin[(size_t)c1 * F4 + f];
        float4 g2 = xin[(size_t)c2 * F4 + f];
        float4 g3 = xin[(size_t)c3 * F4 + f];
        acc.x += w0 * g0.x; acc.y += w0 * g0.y; acc.z += w0 * g0.z; acc.w += w0 * g0.w;
        acc.x += w1 * g1.x; acc.y += w1 * g1.y; acc.z += w1 * g1.z; acc.w += w1 * g1.w;
        acc.x += w2 * g2.x; acc.y += w2 * g2.y; acc.z += w2 * g2.z; acc.w += w2 * g2.w;
        acc.x += w3 * g3.x; acc.y += w3 * g3.y; acc.z += w3 * g3.z; acc.w += w3 * g3.w;
    }
    for (; i < e; i++) {
        int c0 = colS[i]; float w0 = valS[i];
        float4 g0 = xin[(size_t)c0 * F4 + f];
        acc.x += w0 * g0.x; acc.y += w0 * g0.y; acc.z += w0 * g0.z; acc.w += w0 * g0.w;
    }
    if (xprev) {
        float4 pv = xprev[(size_t)v * F4 + f];
        acc.x = 2.f * acc.x - pv.x; acc.y = 2.f * acc.y - pv.y;
        acc.z = 2.f * acc.z - pv.z; acc.w = 2.f * acc.w - pv.w;
    }
    y[(size_t)v * F4 + f] = acc;
}

// ---------------------------------------------------------------------------
// mma.sync bf16x3 Chebyshev GEMM
// A = 10 stacked slots [M, CIN] fp32: slot0=A0, slot k>=1 = Arest+(k-1)*stride.
// out[m,n] = ELU( sum over K=10*CIN of A*W + bias[n] )
// ---------------------------------------------------------------------------
__device__ __forceinline__ void mma16816(float* d, const uint32_t* a, const uint32_t* b) {
    asm volatile(
        "mma.sync.aligned.m16n8k16.row.col.f32.bf16.bf16.f32 "
        "{%0,%1,%2,%3}, {%4,%5,%6,%7}, {%8,%9}, {%0,%1,%2,%3};\n"
        : "+f"(d[0]), "+f"(d[1]), "+f"(d[2]), "+f"(d[3])
        : "r"(a[0]), "r"(a[1]), "r"(a[2]), "r"(a[3]), "r"(b[0]), "r"(b[1]));
}

__device__ __forceinline__ void split_pack2(float x0, float x1, uint32_t& hi, uint32_t& lo) {
    __nv_bfloat16 h0 = __float2bfloat16_rn(x0);
    __nv_bfloat16 h1 = __float2bfloat16_rn(x1);
    __nv_bfloat16 l0 = __float2bfloat16_rn(x0 - __bfloat162float(h0));
    __nv_bfloat16 l1 = __float2bfloat16_rn(x1 - __bfloat162float(h1));
    __nv_bfloat162 hv(h0, h1), lv(l0, l1);
    hi = *(uint32_t*)&hv;
    lo = *(uint32_t*)&lv;
}

template <int CIN, int COUT>
__global__ __launch_bounds__(256)
void k_gemm_mma(const float* __restrict__ A0, const float* __restrict__ Arest,
                size_t slotStride, const float* __restrict__ W,
                const float* __restrict__ bias, float* __restrict__ out) {
    constexpr int NCH = (10 * CIN) / 32;   // K-chunks of 32 fp32 elems (16 words)
    constexpr int NT = COUT / 8;           // n-tiles per warp

    __shared__ uint32_t Ah[128][17];
    __shared__ uint32_t Al[128][17];
    __shared__ uint32_t Bh[COUT][17];
    __shared__ uint32_t Bl[COUT][17];

    int tid = threadIdx.x;
    int lane = tid & 31;
    int w = tid >> 5;
    int mBase = blockIdx.x * 128;

    float acc[NT][4];
#pragma unroll
    for (int j = 0; j < NT; j++)
#pragma unroll
        for (int q = 0; q < 4; q++) acc[j][q] = 0.f;

    for (int c = 0; c < NCH; c++) {
        // ---- stage A tile: 128 rows x 32 k (fp32) -> hi/lo bf16-pair words ----
#pragma unroll
        for (int it = 0; it < 4; it++) {
            int idx = it * 256 + tid;     // 1024 float4-loads total
            int r = idx >> 3;
            int q = idx & 7;              // float4 index: k = 4q..4q+3
            int kk = c * 32 + q * 4;
            int s = kk / CIN;
            int off = kk % CIN;
            const float* src = ((s == 0) ? A0 : (Arest + (size_t)(s - 1) * slotStride))
                               + (size_t)(mBase + r) * CIN + off;
            float4 a = *(const float4*)src;
            uint32_t h0, l0, h1, l1;
            split_pack2(a.x, a.y, h0, l0);
            split_pack2(a.z, a.w, h1, l1);
            Ah[r][2 * q] = h0; Ah[r][2 * q + 1] = h1;
            Al[r][2 * q] = l0; Al[r][2 * q + 1] = l1;
        }
        // ---- stage B tile: n-major [n][k2]; B[n,k] = W[k,n] ----
        for (int idx = tid; idx < COUT * 16; idx += 256) {
            int k2 = idx / COUT;
            int n = idx % COUT;
            int kk = c * 32 + 2 * k2;
            int s = kk / CIN;
            int off = kk % CIN;
            const float* wp = W + ((size_t)s * CIN + off) * COUT + n;
            float w0 = __ldg(wp);
            float w1 = __ldg(wp + COUT);
            uint32_t h, l;
            split_pack2(w0, w1, h, l);
            Bh[n][k2] = h;
            Bl[n][k2] = l;
        }
        __syncthreads();

        // ---- 2 k-steps of 16 ----
#pragma unroll
        for (int ks = 0; ks < 2; ks++) {
            int kq = ks * 8 + (lane & 3);
            int r0 = w * 16 + (lane >> 2);
            uint32_t ah[4], al[4];
            ah[0] = Ah[r0][kq];     ah[1] = Ah[r0 + 8][kq];
            ah[2] = Ah[r0][kq + 4]; ah[3] = Ah[r0 + 8][kq + 4];
            al[0] = Al[r0][kq];     al[1] = Al[r0 + 8][kq];
            al[2] = Al[r0][kq + 4]; al[3] = Al[r0 + 8][kq + 4];
#pragma unroll
            for (int j = 0; j < NT; j++) {
                int n = j * 8 + (lane >> 2);
                uint32_t bh[2] = { Bh[n][kq], Bh[n][kq + 4] };
                uint32_t bl[2] = { Bl[n][kq], Bl[n][kq + 4] };
                mma16816(acc[j], ah, bh);
                mma16816(acc[j], al, bh);
                mma16816(acc[j], ah, bl);
            }
        }
        __syncthreads();
    }

    // ---- epilogue: bias + ELU ----
    int r0 = mBase + w * 16 + (lane >> 2);
#pragma unroll
    for (int j = 0; j < NT; j++) {
        int n = j * 8 + 2 * (lane & 3);
        float b0 = __ldg(&bias[n]);
        float b1 = __ldg(&bias[n + 1]);
        float2 o0 = make_float2(elu1(acc[j][0] + b0), elu1(acc[j][1] + b1));
        float2 o1 = make_float2(elu1(acc[j][2] + b0), elu1(acc[j][3] + b1));
        *(float2*)&out[(size_t)r0 * COUT + n] = o0;
        *(float2*)&out[(size_t)(r0 + 8) * COUT + n] = o1;
    }
}

// CIN=1 special case (level-1 conv1)
__global__ void k_gemm_c1(const float* __restrict__ A0, const float* __restrict__ Arest,
                          size_t slotStride, const float* __restrict__ W,
                          const float* __restrict__ bias, float* __restrict__ out, int M) {
    __shared__ float Ws[10][32];
    __shared__ float bs[32];
    int tid = threadIdx.y * 32 + threadIdx.x;
    for (int t = tid; t < 320; t += 256) Ws[t / 32][t % 32] = W[t];
    if (tid < 32) bs[tid] = bias[tid];
    __syncthreads();
    int m = blockIdx.x * 8 + threadIdx.y;
    int n = threadIdx.x;
    float acc = A0[m] * Ws[0][n];
#pragma unroll
    for (int k = 1; k < 10; k++)
        acc += Arest[(size_t)(k - 1) * slotStride + m] * Ws[k][n];
    out[(size_t)m * 32 + n] = elu1(acc + bs[n]);
}

// ---------------------------------------------------------------------------
// Fused skip-write + pooling
// ---------------------------------------------------------------------------
__global__ void k_skip_pool_next4(const float4* __restrict__ in, float4* __restrict__ skip,
                                  float4* __restrict__ pool, int Vin, int C4) {
    int t = blockIdx.x * blockDim.x + threadIdx.x;
    int F4 = BATCH * C4;
    int n = (Vin / 4) * F4;
    if (t >= n) return;
    int v4 = t / F4;
    int f = t - v4 * F4;
    int b = f / C4;
    int c = f - b * C4;
    const float4* bp = in + (size_t)(4 * v4) * F4 + f;
    float4 a0 = bp[0], a1 = bp[F4], a2 = bp[2 * F4], a3 = bp[3 * F4];
    skip[((size_t)b * Vin + 4 * v4 + 0) * C4 + c] = a0;
    skip[((size_t)b * Vin + 4 * v4 + 1) * C4 + c] = a1;
    skip[((size_t)b * Vin + 4 * v4 + 2) * C4 + c] = a2;
    skip[((size_t)b * Vin + 4 * v4 + 3) * C4 + c] = a3;
    float4 o;
    o.x = 0.25f * (a0.x + a1.x + a2.x + a3.x);
    o.y = 0.25f * (a0.y + a1.y + a2.y + a3.y);
    o.z = 0.25f * (a0.z + a1.z + a2.z + a3.z);
    o.w = 0.25f * (a0.w + a1.w + a2.w + a3.w);
    pool[t] = o;
}
__global__ void k_skip_pool_out4(const float4* __restrict__ in, float4* __restrict__ skip,
                                 float4* __restrict__ poolT, int Vin, int C4) {
    int t = blockIdx.x * blockDim.x + threadIdx.x;
    int F4 = BATCH * C4;
    int Vout = Vin / 4;
    int n = Vout * F4;
    if (t >= n) return;
    int v4 = t / F4;
    int f = t - v4 * F4;
    int b = f / C4;
    int c = f - b * C4;
    const float4* bp = in + (size_t)(4 * v4) * F4 + f;
    float4 a0 = bp[0], a1 = bp[F4], a2 = bp[2 * F4], a3 = bp[3 * F4];
    skip[((size_t)b * Vin + 4 * v4 + 0) * C4 + c] = a0;
    skip[((size_t)b * Vin + 4 * v4 + 1) * C4 + c] = a1;
    skip[((size_t)b * Vin + 4 * v4 + 2) * C4 + c] = a2;
    skip[((size_t)b * Vin + 4 * v4 + 3) * C4 + c] = a3;
    float4 o;
    o.x = 0.25f * (a0.x + a1.x + a2.x + a3.x);
    o.y = 0.25f * (a0.y + a1.y + a2.y + a3.y);
    o.z = 0.25f * (a0.z + a1.z + a2.z + a3.z);
    o.w = 0.25f * (a0.w + a1.w + a2.w + a3.w);
    poolT[((size_t)b * Vout + v4) * C4 + c] = o;
}

// ---------------------------------------------------------------------------
// Host orchestration
// ---------------------------------------------------------------------------
static inline int divUp(int a, int b) { return (a + b - 1) / b; }

struct DevPtrs {
    float* cheb; float* out; float* out2;
    int* rowPtr; int* cursor; int* colS; float* valS; int* orig; int* bsum;
};
static void get_ptrs(DevPtrs& p) {
    cudaGetSymbolAddress((void**)&p.cheb, g_cheb);
    cudaGetSymbolAddress((void**)&p.out, g_out);
    cudaGetSymbolAddress((void**)&p.out2, g_out2);
    cudaGetSymbolAddress((void**)&p.rowPtr, g_rowPtr);
    cudaGetSymbolAddress((void**)&p.cursor, g_cursor);
    cudaGetSymbolAddress((void**)&p.colS, g_colS);
    cudaGetSymbolAddress((void**)&p.valS, g_valS);
    cudaGetSymbolAddress((void**)&p.orig, g_orig);
    cudaGetSymbolAddress((void**)&p.bsum, g_bsum);
}

static void build_csr(const DevPtrs& p, const int* rows, const int* cols, const float* vals,
                      int V, int E) {
    k_zero_int<<<divUp(V + 1, 256), 256>>>(p.cursor, V + 1);
    k_hist<<<divUp(E, 256), 256>>>(rows, p.cursor, E);
    int nb = divUp(V, 1024);
    k_scan_block<<<nb, 1024>>>(p.cursor, p.rowPtr, p.bsum, V);
    k_scan_top<<<1, 64>>>(p.bsum, nb);
    k_scan_add<<<divUp(V + 1, 256), 256>>>(p.rowPtr, p.bsum, V, E);
    k_copy_int<<<divUp(V, 256), 256>>>(p.rowPtr, p.cursor, V);
    k_scatter<<<divUp(E, 256), 256>>>(rows, cols, vals, p.cursor, p.colS, p.valS, p.orig, E);
    k_rowsort<<<divUp(V, 128), 128>>>(p.rowPtr, p.colS, p.valS, p.orig, V);
}

template <int F>
static void spmv_chain(const DevPtrs& p, const float* x0base, int V) {
    constexpr int F4 = F / 4;
    constexpr int ROWS = (F4 >= 256) ? 1 : (256 / F4);
    dim3 blk(F4, ROWS);
    size_t S = (size_t)V * F;
    k_spmv4<F4, ROWS><<<V / ROWS, blk>>>(p.rowPtr, p.colS, p.valS,
                                         (const float4*)x0base, nullptr,
                                         (float4*)(p.cheb + S), V);
    for (int k = 2; k < 10; k++) {
        const float* xk1 = p.cheb + (size_t)(k - 1) * S;
        const float* xk2 = (k == 2) ? x0base : (p.cheb + (size_t)(k - 2) * S);
        k_spmv4<F4, ROWS><<<V / ROWS, blk>>>(p.rowPtr, p.colS, p.valS,
                                             (const float4*)xk1, (const float4*)xk2,
                                             (float4*)(p.cheb + (size_t)k * S), V);
    }
}

extern "C" void kernel_launch(void* const* d_in, const int* in_sizes, int n_in,
                              void* d_out_v, int out_size) {
    (void)in_sizes; (void)n_in; (void)out_size;
    DevPtrs p; get_ptrs(p);

    const float* x    = (const float*)d_in[0];
    const float* w1_1 = (const float*)d_in[1];
    const float* b1_1 = (const float*)d_in[2];
    const float* w2_1 = (const float*)d_in[3];
    const float* b2_1 = (const float*)d_in[4];
    const int*   rows1 = (const int*)d_in[5];
    const int*   cols1 = (const int*)d_in[6];
    const float* vals1 = (const float*)d_in[7];
    const float* w1_2 = (const float*)d_in[8];
    const float* b1_2 = (const float*)d_in[9];
    const float* w2_2 = (const float*)d_in[10];
    const float* b2_2 = (const float*)d_in[11];
    const int*   rows2 = (const int*)d_in[12];
    const int*   cols2 = (const int*)d_in[13];
    const float* vals2 = (const float*)d_in[14];
    const float* w1_3 = (const float*)d_in[15];
    const float* b1_3 = (const float*)d_in[16];
    const float* w2_3 = (const float*)d_in[17];
    const float* b2_3 = (const float*)d_in[18];
    const int*   rows3 = (const int*)d_in[19];
    const int*   cols3 = (const int*)d_in[20];
    const float* vals3 = (const float*)d_in[21];

    float* d_out = (float*)d_out_v;
    float* out_skip1 = d_out;                       // [8,49152,32]
    float* out_skip2 = d_out + (size_t)12582912;    // [8,12288,64]
    float* out_skip3 = out_skip2 + (size_t)6291456; // [8,3072,128]
    float* out_x     = out_skip3 + (size_t)3145728; // [8,768,128]

    // ---------------- Level 1 ----------------
    build_csr(p, rows1, cols1, vals1, V1, E1);
    k_transpose_in<<<divUp(V1, 256), 256>>>(x, p.cheb, V1);
    spmv_chain<8>(p, p.cheb, V1);
    k_gemm_c1<<<V1 * BATCH / 8, dim3(32, 8)>>>(p.cheb, p.cheb + (size_t)V1 * 8,
                                               (size_t)V1 * 8, w1_1, b1_1, p.out, V1 * BATCH);

    spmv_chain<256>(p, p.out, V1);
    k_gemm_mma<32, 32><<<V1 * BATCH / 128, 256>>>(
        p.out, p.cheb + (size_t)V1 * 256, (size_t)V1 * 256, w2_1, b2_1, p.out2);
    {
        int n2 = (V1 / 4) * BATCH * 8;
        k_skip_pool_next4<<<divUp(n2, 256), 256>>>((const float4*)p.out2, (float4*)out_skip1,
                                                   (float4*)p.cheb, V1, 8);
    }

    // ---------------- Level 2 ----------------
    build_csr(p, rows2, cols2, vals2, V2, E2);
    spmv_chain<256>(p, p.cheb, V2);
    k_gemm_mma<32, 64><<<V2 * BATCH / 128, 256>>>(
        p.cheb, p.cheb + (size_t)V2 * 256, (size_t)V2 * 256, w1_2, b1_2, p.out);

    spmv_chain<512>(p, p.out, V2);
    k_gemm_mma<64, 64><<<V2 * BATCH / 128, 256>>>(
        p.out, p.cheb + (size_t)V2 * 512, (size_t)V2 * 512, w2_2, b2_2, p.out2);
    {
        int n2 = (V2 / 4) * BATCH * 16;
        k_skip_pool_next4<<<divUp(n2, 256), 256>>>((const float4*)p.out2, (float4*)out_skip2,
                                                   (float4*)p.cheb, V2, 16);
    }

    // ---------------- Level 3 ----------------
    build_csr(p, rows3, cols3, vals3, V3, E3);
    spmv_chain<512>(p, p.cheb, V3);
    k_gemm_mma<64, 128><<<V3 * BATCH / 128, 256>>>(
        p.cheb, p.cheb + (size_t)V3 * 512, (size_t)V3 * 512, w1_3, b1_3, p.out);

    spmv_chain<1024>(p, p.out, V3);
    k_gemm_mma<128, 128><<<V3 * BATCH / 128, 256>>>(
        p.out, p.cheb + (size_t)V3 * 1024, (size_t)V3 * 1024, w2_3, b2_3, p.out2);
    {
        int n2 = (V3 / 4) * BATCH * 32;
        k_skip_pool_out4<<<divUp(n2, 256), 256>>>((const float4*)p.out2, (float4*)out_skip3,
                                                  (float4*)out_x, V3, 32);
    }
}

// round 6
// speedup vs baseline: 3.2625x; 1.0259x over previous
#include <cuda_runtime.h>
#include <cuda_bf16.h>
#include <cstdint>
#include <cstdio>

#define BATCH 8
#define V1 49152
#define V2 12288
#define V3 3072
#define E1 393216
#define E2 98304
#define E3 24576

// Scratch (device globals; allocation-free rule)
__device__ float g_cheb[125829120];   // 10 * 49152 * 256 floats
__device__ float g_out[12582912];
__device__ float g_out2[12582912];
__device__ int   g_rowPtr[V1 + 1];
__device__ int   g_cursor[V1 + 1];
__device__ int   g_colS[E1];
__device__ float g_valS[E1];
__device__ int   g_orig[E1];
__device__ int   g_bsum[64];

__device__ __forceinline__ float elu1(float x) { return x > 0.f ? x : expm1f(x); }

// ---------------------------------------------------------------------------
// Utility kernels
// ---------------------------------------------------------------------------
__global__ void k_zero_int(int* p, int n) {
    int i = blockIdx.x * blockDim.x + threadIdx.x;
    if (i < n) p[i] = 0;
}
__global__ void k_transpose_in(const float* __restrict__ x, float* __restrict__ out, int V) {
    int v = blockIdx.x * blockDim.x + threadIdx.x;
    if (v < V) {
#pragma unroll
        for (int b = 0; b < BATCH; b++)
            out[(size_t)v * BATCH + b] = x[(size_t)b * V + v];
    }
}

// ---------------------------------------------------------------------------
// CSR build (deterministic)
// ---------------------------------------------------------------------------
__global__ void k_hist(const int* __restrict__ rows, int* cnt, int E) {
    int e = blockIdx.x * blockDim.x + threadIdx.x;
    if (e < E) atomicAdd(&cnt[rows[e]], 1);
}
__global__ void k_scan_block(const int* __restrict__ cnt, int* __restrict__ outEx,
                             int* __restrict__ bsum, int V) {
    __shared__ int s[1024];
    int tid = threadIdx.x;
    int i = blockIdx.x * 1024 + tid;
    int v = (i < V) ? cnt[i] : 0;
    s[tid] = v;
    __syncthreads();
    for (int off = 1; off < 1024; off <<= 1) {
        int t = 0;
        if (tid >= off) t = s[tid - off];
        __syncthreads();
        s[tid] += t;
        __syncthreads();
    }
    if (i < V) outEx[i] = s[tid] - v;
    if (tid == 1023) bsum[blockIdx.x] = s[1023];
}
__global__ void k_scan_top(int* bsum, int nb) {
    __shared__ int s[64];
    int t = threadIdx.x;
    int v = (t < nb) ? bsum[t] : 0;
    s[t] = v;
    __syncthreads();
    for (int off = 1; off < 64; off <<= 1) {
        int x = (t >= off) ? s[t - off] : 0;
        __syncthreads();
        s[t] += x;
        __syncthreads();
    }
    if (t < nb) bsum[t] = s[t] - v;
}
// adds block offsets AND seeds the scatter cursor (merged copy)
__global__ void k_scan_add(int* rowPtr, int* cursor, const int* __restrict__ bsum,
                           int V, int E) {
    int i = blockIdx.x * blockDim.x + threadIdx.x;
    if (i < V) {
        int val = rowPtr[i] + bsum[i >> 10];
        rowPtr[i] = val;
        cursor[i] = val;
    }
    if (i == 0) rowPtr[V] = E;
}
__global__ void k_scatter(const int* __restrict__ rows, const int* __restrict__ cols,
                          const float* __restrict__ vals, int* cursor,
                          int* colS, float* valS, int* orig, int E) {
    int e = blockIdx.x * blockDim.x + threadIdx.x;
    if (e < E) {
        int r = rows[e];
        int pos = atomicAdd(&cursor[r], 1);
        colS[pos] = cols[e];
        valS[pos] = vals[e];
        orig[pos] = e;
    }
}
__global__ void k_rowsort(const int* __restrict__ rowPtr, int* colS, float* valS, int* orig, int V) {
    int v = blockIdx.x * blockDim.x + threadIdx.x;
    if (v >= V) return;
    int s = rowPtr[v], e = rowPtr[v + 1];
    for (int i = s + 1; i < e; i++) {
        int ko = orig[i]; int kc = colS[i]; float kv = valS[i];
        int j = i - 1;
        while (j >= s && orig[j] > ko) {
            orig[j + 1] = orig[j]; colS[j + 1] = colS[j]; valS[j + 1] = valS[j];
            j--;
        }
        orig[j + 1] = ko; colS[j + 1] = kc; valS[j + 1] = kv;
    }
}

// ---------------------------------------------------------------------------
// SpMV (float4, 4-edge unrolled, runtime row-stride F4S for feature-split)
// ---------------------------------------------------------------------------
template <int F4, int ROWS, bool HASPREV>
__global__ void k_spmv4(const int* __restrict__ rowPtr, const int* __restrict__ colS,
                        const float* __restrict__ valS,
                        const float4* __restrict__ xin, const float4* __restrict__ xprev,
                        float4* __restrict__ y, int V, int F4S) {
    int f = threadIdx.x;
    int v = blockIdx.x * ROWS + threadIdx.y;
    int s = rowPtr[v], e = rowPtr[v + 1];
    float4 acc = make_float4(0.f, 0.f, 0.f, 0.f);
    int i = s;
    for (; i + 4 <= e; i += 4) {
        int c0 = colS[i];     float w0 = valS[i];
        int c1 = colS[i + 1]; float w1 = valS[i + 1];
        int c2 = colS[i + 2]; float w2 = valS[i + 2];
        int c3 = colS[i + 3]; float w3 = valS[i + 3];
        float4 g0 = xin[(size_t)c0 * F4S + f];
        float4 g1 = xin[(size_t)c1 * F4S + f];
        float4 g2 = xin[(size_t)c2 * F4S + f];
        float4 g3 = xin[(size_t)c3 * F4S + f];
        acc.x += w0 * g0.x; acc.y += w0 * g0.y; acc.z += w0 * g0.z; acc.w += w0 * g0.w;
        acc.x += w1 * g1.x; acc.y += w1 * g1.y; acc.z += w1 * g1.z; acc.w += w1 * g1.w;
        acc.x += w2 * g2.x; acc.y += w2 * g2.y; acc.z += w2 * g2.z; acc.w += w2 * g2.w;
        acc.x += w3 * g3.x; acc.y += w3 * g3.y; acc.z += w3 * g3.z; acc.w += w3 * g3.w;
    }
    for (; i < e; i++) {
        int c0 = colS[i]; float w0 = valS[i];
        float4 g0 = xin[(size_t)c0 * F4S + f];
        acc.x += w0 * g0.x; acc.y += w0 * g0.y; acc.z += w0 * g0.z; acc.w += w0 * g0.w;
    }
    if (HASPREV) {
        float4 pv = xprev[(size_t)v * F4S + f];
        acc.x = 2.f * acc.x - pv.x; acc.y = 2.f * acc.y - pv.y;
        acc.z = 2.f * acc.z - pv.z; acc.w = 2.f * acc.w - pv.w;
    }
    y[(size_t)v * F4S + f] = acc;
}

// ---------------------------------------------------------------------------
// mma.sync bf16x3 Chebyshev GEMM (unchanged from R5 — verified)
// ---------------------------------------------------------------------------
__device__ __forceinline__ void mma16816(float* d, const uint32_t* a, const uint32_t* b) {
    asm volatile(
        "mma.sync.aligned.m16n8k16.row.col.f32.bf16.bf16.f32 "
        "{%0,%1,%2,%3}, {%4,%5,%6,%7}, {%8,%9}, {%0,%1,%2,%3};\n"
        : "+f"(d[0]), "+f"(d[1]), "+f"(d[2]), "+f"(d[3])
        : "r"(a[0]), "r"(a[1]), "r"(a[2]), "r"(a[3]), "r"(b[0]), "r"(b[1]));
}

__device__ __forceinline__ void split_pack2(float x0, float x1, uint32_t& hi, uint32_t& lo) {
    __nv_bfloat16 h0 = __float2bfloat16_rn(x0);
    __nv_bfloat16 h1 = __float2bfloat16_rn(x1);
    __nv_bfloat16 l0 = __float2bfloat16_rn(x0 - __bfloat162float(h0));
    __nv_bfloat16 l1 = __float2bfloat16_rn(x1 - __bfloat162float(h1));
    __nv_bfloat162 hv(h0, h1), lv(l0, l1);
    hi = *(uint32_t*)&hv;
    lo = *(uint32_t*)&lv;
}

template <int CIN, int COUT>
__global__ __launch_bounds__(256)
void k_gemm_mma(const float* __restrict__ A0, const float* __restrict__ Arest,
                size_t slotStride, const float* __restrict__ W,
                const float* __restrict__ bias, float* __restrict__ out) {
    constexpr int NCH = (10 * CIN) / 32;
    constexpr int NT = COUT / 8;

    __shared__ uint32_t Ah[128][17];
    __shared__ uint32_t Al[128][17];
    __shared__ uint32_t Bh[COUT][17];
    __shared__ uint32_t Bl[COUT][17];

    int tid = threadIdx.x;
    int lane = tid & 31;
    int w = tid >> 5;
    int mBase = blockIdx.x * 128;

    float acc[NT][4];
#pragma unroll
    for (int j = 0; j < NT; j++)
#pragma unroll
        for (int q = 0; q < 4; q++) acc[j][q] = 0.f;

    for (int c = 0; c < NCH; c++) {
#pragma unroll
        for (int it = 0; it < 4; it++) {
            int idx = it * 256 + tid;
            int r = idx >> 3;
            int q = idx & 7;
            int kk = c * 32 + q * 4;
            int s = kk / CIN;
            int off = kk % CIN;
            const float* src = ((s == 0) ? A0 : (Arest + (size_t)(s - 1) * slotStride))
                               + (size_t)(mBase + r) * CIN + off;
            float4 a = *(const float4*)src;
            uint32_t h0, l0, h1, l1;
            split_pack2(a.x, a.y, h0, l0);
            split_pack2(a.z, a.w, h1, l1);
            Ah[r][2 * q] = h0; Ah[r][2 * q + 1] = h1;
            Al[r][2 * q] = l0; Al[r][2 * q + 1] = l1;
        }
        for (int idx = tid; idx < COUT * 16; idx += 256) {
            int k2 = idx / COUT;
            int n = idx % COUT;
            int kk = c * 32 + 2 * k2;
            int s = kk / CIN;
            int off = kk % CIN;
            const float* wp = W + ((size_t)s * CIN + off) * COUT + n;
            float w0 = __ldg(wp);
            float w1 = __ldg(wp + COUT);
            uint32_t h, l;
            split_pack2(w0, w1, h, l);
            Bh[n][k2] = h;
            Bl[n][k2] = l;
        }
        __syncthreads();

#pragma unroll
        for (int ks = 0; ks < 2; ks++) {
            int kq = ks * 8 + (lane & 3);
            int r0 = w * 16 + (lane >> 2);
            uint32_t ah[4], al[4];
            ah[0] = Ah[r0][kq];     ah[1] = Ah[r0 + 8][kq];
            ah[2] = Ah[r0][kq + 4]; ah[3] = Ah[r0 + 8][kq + 4];
            al[0] = Al[r0][kq];     al[1] = Al[r0 + 8][kq];
            al[2] = Al[r0][kq + 4]; al[3] = Al[r0 + 8][kq + 4];
#pragma unroll
            for (int j = 0; j < NT; j++) {
                int n = j * 8 + (lane >> 2);
                uint32_t bh[2] = { Bh[n][kq], Bh[n][kq + 4] };
                uint32_t bl[2] = { Bl[n][kq], Bl[n][kq + 4] };
                mma16816(acc[j], ah, bh);
                mma16816(acc[j], al, bh);
                mma16816(acc[j], ah, bl);
            }
        }
        __syncthreads();
    }

    int r0 = mBase + w * 16 + (lane >> 2);
#pragma unroll
    for (int j = 0; j < NT; j++) {
        int n = j * 8 + 2 * (lane & 3);
        float b0 = __ldg(&bias[n]);
        float b1 = __ldg(&bias[n + 1]);
        float2 o0 = make_float2(elu1(acc[j][0] + b0), elu1(acc[j][1] + b1));
        float2 o1 = make_float2(elu1(acc[j][2] + b0), elu1(acc[j][3] + b1));
        *(float2*)&out[(size_t)r0 * COUT + n] = o0;
        *(float2*)&out[(size_t)(r0 + 8) * COUT + n] = o1;
    }
}

// CIN=1 special case (level-1 conv1)
__global__ void k_gemm_c1(const float* __restrict__ A0, const float* __restrict__ Arest,
                          size_t slotStride, const float* __restrict__ W,
                          const float* __restrict__ bias, float* __restrict__ out, int M) {
    __shared__ float Ws[10][32];
    __shared__ float bs[32];
    int tid = threadIdx.y * 32 + threadIdx.x;
    for (int t = tid; t < 320; t += 256) Ws[t / 32][t % 32] = W[t];
    if (tid < 32) bs[tid] = bias[tid];
    __syncthreads();
    int m = blockIdx.x * 8 + threadIdx.y;
    int n = threadIdx.x;
    float acc = A0[m] * Ws[0][n];
#pragma unroll
    for (int k = 1; k < 10; k++)
        acc += Arest[(size_t)(k - 1) * slotStride + m] * Ws[k][n];
    out[(size_t)m * 32 + n] = elu1(acc + bs[n]);
}

// ---------------------------------------------------------------------------
// Fused skip-write + pooling
// ---------------------------------------------------------------------------
__global__ void k_skip_pool_next4(const float4* __restrict__ in, float4* __restrict__ skip,
                                  float4* __restrict__ pool, int Vin, int C4) {
    int t = blockIdx.x * blockDim.x + threadIdx.x;
    int F4 = BATCH * C4;
    int n = (Vin / 4) * F4;
    if (t >= n) return;
    int v4 = t / F4;
    int f = t - v4 * F4;
    int b = f / C4;
    int c = f - b * C4;
    const float4* bp = in + (size_t)(4 * v4) * F4 + f;
    float4 a0 = bp[0], a1 = bp[F4], a2 = bp[2 * F4], a3 = bp[3 * F4];
    skip[((size_t)b * Vin + 4 * v4 + 0) * C4 + c] = a0;
    skip[((size_t)b * Vin + 4 * v4 + 1) * C4 + c] = a1;
    skip[((size_t)b * Vin + 4 * v4 + 2) * C4 + c] = a2;
    skip[((size_t)b * Vin + 4 * v4 + 3) * C4 + c] = a3;
    float4 o;
    o.x = 0.25f * (a0.x + a1.x + a2.x + a3.x);
    o.y = 0.25f * (a0.y + a1.y + a2.y + a3.y);
    o.z = 0.25f * (a0.z + a1.z + a2.z + a3.z);
    o.w = 0.25f * (a0.w + a1.w + a2.w + a3.w);
    pool[t] = o;
}
__global__ void k_skip_pool_out4(const float4* __restrict__ in, float4* __restrict__ skip,
                                 float4* __restrict__ poolT, int Vin, int C4) {
    int t = blockIdx.x * blockDim.x + threadIdx.x;
    int F4 = BATCH * C4;
    int Vout = Vin / 4;
    int n = Vout * F4;
    if (t >= n) return;
    int v4 = t / F4;
    int f = t - v4 * F4;
    int b = f / C4;
    int c = f - b * C4;
    const float4* bp = in + (size_t)(4 * v4) * F4 + f;
    float4 a0 = bp[0], a1 = bp[F4], a2 = bp[2 * F4], a3 = bp[3 * F4];
    skip[((size_t)b * Vin + 4 * v4 + 0) * C4 + c] = a0;
    skip[((size_t)b * Vin + 4 * v4 + 1) * C4 + c] = a1;
    skip[((size_t)b * Vin + 4 * v4 + 2) * C4 + c] = a2;
    skip[((size_t)b * Vin + 4 * v4 + 3) * C4 + c] = a3;
    float4 o;
    o.x = 0.25f * (a0.x + a1.x + a2.x + a3.x);
    o.y = 0.25f * (a0.y + a1.y + a2.y + a3.y);
    o.z = 0.25f * (a0.z + a1.z + a2.z + a3.z);
    o.w = 0.25f * (a0.w + a1.w + a2.w + a3.w);
    poolT[((size_t)b * Vout + v4) * C4 + c] = o;
}

// ---------------------------------------------------------------------------
// Host orchestration
// ---------------------------------------------------------------------------
static inline int divUp(int a, int b) { return (a + b - 1) / b; }

struct DevPtrs {
    float* cheb; float* out; float* out2;
    int* rowPtr; int* cursor; int* colS; float* valS; int* orig; int* bsum;
};
static void get_ptrs(DevPtrs& p) {
    cudaGetSymbolAddress((void**)&p.cheb, g_cheb);
    cudaGetSymbolAddress((void**)&p.out, g_out);
    cudaGetSymbolAddress((void**)&p.out2, g_out2);
    cudaGetSymbolAddress((void**)&p.rowPtr, g_rowPtr);
    cudaGetSymbolAddress((void**)&p.cursor, g_cursor);
    cudaGetSymbolAddress((void**)&p.colS, g_colS);
    cudaGetSymbolAddress((void**)&p.valS, g_valS);
    cudaGetSymbolAddress((void**)&p.orig, g_orig);
    cudaGetSymbolAddress((void**)&p.bsum, g_bsum);
}

static void build_csr(const DevPtrs& p, const int* rows, const int* cols, const float* vals,
                      int V, int E) {
    k_zero_int<<<divUp(V + 1, 256), 256>>>(p.cursor, V + 1);
    k_hist<<<divUp(E, 256), 256>>>(rows, p.cursor, E);
    int nb = divUp(V, 1024);
    k_scan_block<<<nb, 1024>>>(p.cursor, p.rowPtr, p.bsum, V);
    k_scan_top<<<1, 64>>>(p.bsum, nb);
    k_scan_add<<<divUp(V + 1, 256), 256>>>(p.rowPtr, p.cursor, p.bsum, V, E);
    k_scatter<<<divUp(E, 256), 256>>>(rows, cols, vals, p.cursor, p.colS, p.valS, p.orig, E);
    k_rowsort<<<divUp(V, 256), 256>>>(p.rowPtr, p.colS, p.valS, p.orig, V);
}

// Chebyshev chain over feature sub-range: F = features processed per pass,
// FTOT = total row width. f4off = offset into each row (float4 units).
// slot0 = x0base (external), slots 1..9 at cheb + k*V*FTOT.
template <int F, int FTOT>
static void spmv_chain_off(const DevPtrs& p, const float* x0base, int V, int f4off) {
    constexpr int F4 = F / 4;
    constexpr int ROWS = (F4 >= 256) ? 1 : (256 / F4);
    constexpr int F4S = FTOT / 4;
    dim3 blk(F4, ROWS);
    size_t S4 = (size_t)V * F4S;   // slot stride in float4
    const float4* x0 = (const float4*)x0base + f4off;
    float4* cheb = (float4*)p.cheb + f4off;
    k_spmv4<F4, ROWS, false><<<V / ROWS, blk>>>(p.rowPtr, p.colS, p.valS,
                                                x0, nullptr, cheb + S4, V, F4S);
    for (int k = 2; k < 10; k++) {
        const float4* xk1 = cheb + (size_t)(k - 1) * S4;
        const float4* xk2 = (k == 2) ? x0 : (cheb + (size_t)(k - 2) * S4);
        k_spmv4<F4, ROWS, true><<<V / ROWS, blk>>>(p.rowPtr, p.colS, p.valS,
                                                   xk1, xk2, cheb + (size_t)k * S4, V, F4S);
    }
}

extern "C" void kernel_launch(void* const* d_in, const int* in_sizes, int n_in,
                              void* d_out_v, int out_size) {
    (void)in_sizes; (void)n_in; (void)out_size;
    DevPtrs p; get_ptrs(p);

    const float* x    = (const float*)d_in[0];
    const float* w1_1 = (const float*)d_in[1];
    const float* b1_1 = (const float*)d_in[2];
    const float* w2_1 = (const float*)d_in[3];
    const float* b2_1 = (const float*)d_in[4];
    const int*   rows1 = (const int*)d_in[5];
    const int*   cols1 = (const int*)d_in[6];
    const float* vals1 = (const float*)d_in[7];
    const float* w1_2 = (const float*)d_in[8];
    const float* b1_2 = (const float*)d_in[9];
    const float* w2_2 = (const float*)d_in[10];
    const float* b2_2 = (const float*)d_in[11];
    const int*   rows2 = (const int*)d_in[12];
    const int*   cols2 = (const int*)d_in[13];
    const float* vals2 = (const float*)d_in[14];
    const float* w1_3 = (const float*)d_in[15];
    const float* b1_3 = (const float*)d_in[16];
    const float* w2_3 = (const float*)d_in[17];
    const float* b2_3 = (const float*)d_in[18];
    const int*   rows3 = (const int*)d_in[19];
    const int*   cols3 = (const int*)d_in[20];
    const float* vals3 = (const float*)d_in[21];

    float* d_out = (float*)d_out_v;
    float* out_skip1 = d_out;                       // [8,49152,32]
    float* out_skip2 = d_out + (size_t)12582912;    // [8,12288,64]
    float* out_skip3 = out_skip2 + (size_t)6291456; // [8,3072,128]
    float* out_x     = out_skip3 + (size_t)3145728; // [8,768,128]

    // ---------------- Level 1 ----------------
    build_csr(p, rows1, cols1, vals1, V1, E1);
    k_transpose_in<<<divUp(V1, 256), 256>>>(x, p.cheb, V1);
    spmv_chain_off<8, 8>(p, p.cheb, V1, 0);
    k_gemm_c1<<<V1 * BATCH / 8, dim3(32, 8)>>>(p.cheb, p.cheb + (size_t)V1 * 8,
                                               (size_t)V1 * 8, w1_1, b1_1, p.out, V1 * BATCH);

    // level-1 conv2 chain: feature-split into two F=128 halves for L2 residency
    spmv_chain_off<128, 256>(p, p.out, V1, 0);
    spmv_chain_off<128, 256>(p, p.out, V1, 32);
    k_gemm_mma<32, 32><<<V1 * BATCH / 128, 256>>>(
        p.out, p.cheb + (size_t)V1 * 256, (size_t)V1 * 256, w2_1, b2_1, p.out2);
    {
        int n2 = (V1 / 4) * BATCH * 8;
        k_skip_pool_next4<<<divUp(n2, 256), 256>>>((const float4*)p.out2, (float4*)out_skip1,
                                                   (float4*)p.cheb, V1, 8);
    }

    // ---------------- Level 2 ----------------
    build_csr(p, rows2, cols2, vals2, V2, E2);
    spmv_chain_off<256, 256>(p, p.cheb, V2, 0);
    k_gemm_mma<32, 64><<<V2 * BATCH / 128, 256>>>(
        p.cheb, p.cheb + (size_t)V2 * 256, (size_t)V2 * 256, w1_2, b1_2, p.out);

    spmv_chain_off<512, 512>(p, p.out, V2, 0);
    k_gemm_mma<64, 64><<<V2 * BATCH / 128, 256>>>(
        p.out, p.cheb + (size_t)V2 * 512, (size_t)V2 * 512, w2_2, b2_2, p.out2);
    {
        int n2 = (V2 / 4) * BATCH * 16;
        k_skip_pool_next4<<<divUp(n2, 256), 256>>>((const float4*)p.out2, (float4*)out_skip2,
                                                   (float4*)p.cheb, V2, 16);
    }

    // ---------------- Level 3 ----------------
    build_csr(p, rows3, cols3, vals3, V3, E3);
    spmv_chain_off<512, 512>(p, p.cheb, V3, 0);
    k_gemm_mma<64, 128><<<V3 * BATCH / 128, 256>>>(
        p.cheb, p.cheb + (size_t)V3 * 512, (size_t)V3 * 512, w1_3, b1_3, p.out);

    spmv_chain_off<1024, 1024>(p, p.out, V3, 0);
    k_gemm_mma<128, 128><<<V3 * BATCH / 128, 256>>>(
        p.out, p.cheb + (size_t)V3 * 1024, (size_t)V3 * 1024, w2_3, b2_3, p.out2);
    {
        int n2 = (V3 / 4) * BATCH * 32;
        k_skip_pool_out4<<<divUp(n2, 256), 256>>>((const float4*)p.out2, (float4*)out_skip3,
                                                  (float4*)out_x, V3, 32);
    }
}

// round 7
// speedup vs baseline: 3.3375x; 1.0230x over previous
#include <cuda_runtime.h>
#include <cuda_bf16.h>
#include <cstdint>
#include <cstdio>

#define BATCH 8
#define V1 49152
#define V2 12288
#define V3 3072
#define E1 393216
#define E2 98304
#define E3 24576

// Scratch (device globals; allocation-free rule)
__device__ float g_cheb[125829120];   // 10 * 49152 * 256 floats
__device__ float g_out[12582912];
__device__ float g_out2[12582912];
// per-level CSR buffers (enables concurrent builds)
__device__ int   g_rowPtr1[V1 + 1];  __device__ int g_cursor1[V1 + 1];
__device__ int   g_colS1[E1];        __device__ float g_valS1[E1];
__device__ int   g_orig1[E1];        __device__ int g_bsum1[64];
__device__ int   g_rowPtr2[V2 + 1];  __device__ int g_cursor2[V2 + 1];
__device__ int   g_colS2[E2];        __device__ float g_valS2[E2];
__device__ int   g_orig2[E2];        __device__ int g_bsum2[64];
__device__ int   g_rowPtr3[V3 + 1];  __device__ int g_cursor3[V3 + 1];
__device__ int   g_colS3[E3];        __device__ float g_valS3[E3];
__device__ int   g_orig3[E3];        __device__ int g_bsum3[64];

__device__ __forceinline__ float elu1(float x) { return x > 0.f ? x : expm1f(x); }

// ---------------------------------------------------------------------------
// Utility kernels
// ---------------------------------------------------------------------------
__global__ void k_zero_int(int* p, int n) {
    int i = blockIdx.x * blockDim.x + threadIdx.x;
    if (i < n) p[i] = 0;
}
__global__ void k_transpose_in(const float* __restrict__ x, float* __restrict__ out, int V) {
    int v = blockIdx.x * blockDim.x + threadIdx.x;
    if (v < V) {
#pragma unroll
        for (int b = 0; b < BATCH; b++)
            out[(size_t)v * BATCH + b] = x[(size_t)b * V + v];
    }
}

// ---------------------------------------------------------------------------
// CSR build (deterministic)
// ---------------------------------------------------------------------------
__global__ void k_hist(const int* __restrict__ rows, int* cnt, int E) {
    int e = blockIdx.x * blockDim.x + threadIdx.x;
    if (e < E) atomicAdd(&cnt[rows[e]], 1);
}
__global__ void k_scan_block(const int* __restrict__ cnt, int* __restrict__ outEx,
                             int* __restrict__ bsum, int V) {
    __shared__ int s[1024];
    int tid = threadIdx.x;
    int i = blockIdx.x * 1024 + tid;
    int v = (i < V) ? cnt[i] : 0;
    s[tid] = v;
    __syncthreads();
    for (int off = 1; off < 1024; off <<= 1) {
        int t = 0;
        if (tid >= off) t = s[tid - off];
        __syncthreads();
        s[tid] += t;
        __syncthreads();
    }
    if (i < V) outEx[i] = s[tid] - v;
    if (tid == 1023) bsum[blockIdx.x] = s[1023];
}
__global__ void k_scan_top(int* bsum, int nb) {
    __shared__ int s[64];
    int t = threadIdx.x;
    int v = (t < nb) ? bsum[t] : 0;
    s[t] = v;
    __syncthreads();
    for (int off = 1; off < 64; off <<= 1) {
        int x = (t >= off) ? s[t - off] : 0;
        __syncthreads();
        s[t] += x;
        __syncthreads();
    }
    if (t < nb) bsum[t] = s[t] - v;
}
__global__ void k_scan_add(int* rowPtr, int* cursor, const int* __restrict__ bsum,
                           int V, int E) {
    int i = blockIdx.x * blockDim.x + threadIdx.x;
    if (i < V) {
        int val = rowPtr[i] + bsum[i >> 10];
        rowPtr[i] = val;
        cursor[i] = val;
    }
    if (i == 0) rowPtr[V] = E;
}
__global__ void k_scatter(const int* __restrict__ rows, const int* __restrict__ cols,
                          const float* __restrict__ vals, int* cursor,
                          int* colS, float* valS, int* orig, int E) {
    int e = blockIdx.x * blockDim.x + threadIdx.x;
    if (e < E) {
        int r = rows[e];
        int pos = atomicAdd(&cursor[r], 1);
        colS[pos] = cols[e];
        valS[pos] = vals[e];
        orig[pos] = e;
    }
}
__global__ void k_rowsort(const int* __restrict__ rowPtr, int* colS, float* valS, int* orig, int V) {
    int v = blockIdx.x * blockDim.x + threadIdx.x;
    if (v >= V) return;
    int s = rowPtr[v], e = rowPtr[v + 1];
    for (int i = s + 1; i < e; i++) {
        int ko = orig[i]; int kc = colS[i]; float kv = valS[i];
        int j = i - 1;
        while (j >= s && orig[j] > ko) {
            orig[j + 1] = orig[j]; colS[j + 1] = colS[j]; valS[j + 1] = valS[j];
            j--;
        }
        orig[j + 1] = ko; colS[j + 1] = kc; valS[j + 1] = kv;
    }
}

// ---------------------------------------------------------------------------
// SpMV (float4, 4-edge unrolled, runtime row-stride F4S for feature-split)
// ---------------------------------------------------------------------------
template <int F4, int ROWS, bool HASPREV>
__global__ void k_spmv4(const int* __restrict__ rowPtr, const int* __restrict__ colS,
                        const float* __restrict__ valS,
                        const float4* __restrict__ xin, const float4* __restrict__ xprev,
                        float4* __restrict__ y, int V, int F4S) {
    int f = threadIdx.x;
    int v = blockIdx.x * ROWS + threadIdx.y;
    int s = rowPtr[v], e = rowPtr[v + 1];
    float4 acc = make_float4(0.f, 0.f, 0.f, 0.f);
    int i = s;
    for (; i + 4 <= e; i += 4) {
        int c0 = colS[i];     float w0 = valS[i];
        int c1 = colS[i + 1]; float w1 = valS[i + 1];
        int c2 = colS[i + 2]; float w2 = valS[i + 2];
        int c3 = colS[i + 3]; float w3 = valS[i + 3];
        float4 g0 = xin[(size_t)c0 * F4S + f];
        float4 g1 = xin[(size_t)c1 * F4S + f];
        float4 g2 = xin[(size_t)c2 * F4S + f];
        float4 g3 = xin[(size_t)c3 * F4S + f];
        acc.x += w0 * g0.x; acc.y += w0 * g0.y; acc.z += w0 * g0.z; acc.w += w0 * g0.w;
        acc.x += w1 * g1.x; acc.y += w1 * g1.y; acc.z += w1 * g1.z; acc.w += w1 * g1.w;
        acc.x += w2 * g2.x; acc.y += w2 * g2.y; acc.z += w2 * g2.z; acc.w += w2 * g2.w;
        acc.x += w3 * g3.x; acc.y += w3 * g3.y; acc.z += w3 * g3.z; acc.w += w3 * g3.w;
    }
    for (; i < e; i++) {
        int c0 = colS[i]; float w0 = valS[i];
        float4 g0 = xin[(size_t)c0 * F4S + f];
        acc.x += w0 * g0.x; acc.y += w0 * g0.y; acc.z += w0 * g0.z; acc.w += w0 * g0.w;
    }
    if (HASPREV) {
        float4 pv = xprev[(size_t)v * F4S + f];
        acc.x = 2.f * acc.x - pv.x; acc.y = 2.f * acc.y - pv.y;
        acc.z = 2.f * acc.z - pv.z; acc.w = 2.f * acc.w - pv.w;
    }
    y[(size_t)v * F4S + f] = acc;
}

// ---------------------------------------------------------------------------
// mma.sync bf16x3 Chebyshev GEMM (verified in R5/R6)
// ---------------------------------------------------------------------------
__device__ __forceinline__ void mma16816(float* d, const uint32_t* a, const uint32_t* b) {
    asm volatile(
        "mma.sync.aligned.m16n8k16.row.col.f32.bf16.bf16.f32 "
        "{%0,%1,%2,%3}, {%4,%5,%6,%7}, {%8,%9}, {%0,%1,%2,%3};\n"
        : "+f"(d[0]), "+f"(d[1]), "+f"(d[2]), "+f"(d[3])
        : "r"(a[0]), "r"(a[1]), "r"(a[2]), "r"(a[3]), "r"(b[0]), "r"(b[1]));
}

__device__ __forceinline__ void split_pack2(float x0, float x1, uint32_t& hi, uint32_t& lo) {
    __nv_bfloat16 h0 = __float2bfloat16_rn(x0);
    __nv_bfloat16 h1 = __float2bfloat16_rn(x1);
    __nv_bfloat16 l0 = __float2bfloat16_rn(x0 - __bfloat162float(h0));
    __nv_bfloat16 l1 = __float2bfloat16_rn(x1 - __bfloat162float(h1));
    __nv_bfloat162 hv(h0, h1), lv(l0, l1);
    hi = *(uint32_t*)&hv;
    lo = *(uint32_t*)&lv;
}

template <int CIN, int COUT>
__global__ __launch_bounds__(256)
void k_gemm_mma(const float* __restrict__ A0, const float* __restrict__ Arest,
                size_t slotStride, const float* __restrict__ W,
                const float* __restrict__ bias, float* __restrict__ out) {
    constexpr int NCH = (10 * CIN) / 32;
    constexpr int NT = COUT / 8;

    __shared__ uint32_t Ah[128][17];
    __shared__ uint32_t Al[128][17];
    __shared__ uint32_t Bh[COUT][17];
    __shared__ uint32_t Bl[COUT][17];

    int tid = threadIdx.x;
    int lane = tid & 31;
    int w = tid >> 5;
    int mBase = blockIdx.x * 128;

    float acc[NT][4];
#pragma unroll
    for (int j = 0; j < NT; j++)
#pragma unroll
        for (int q = 0; q < 4; q++) acc[j][q] = 0.f;

    for (int c = 0; c < NCH; c++) {
#pragma unroll
        for (int it = 0; it < 4; it++) {
            int idx = it * 256 + tid;
            int r = idx >> 3;
            int q = idx & 7;
            int kk = c * 32 + q * 4;
            int s = kk / CIN;
            int off = kk % CIN;
            const float* src = ((s == 0) ? A0 : (Arest + (size_t)(s - 1) * slotStride))
                               + (size_t)(mBase + r) * CIN + off;
            float4 a = *(const float4*)src;
            uint32_t h0, l0, h1, l1;
            split_pack2(a.x, a.y, h0, l0);
            split_pack2(a.z, a.w, h1, l1);
            Ah[r][2 * q] = h0; Ah[r][2 * q + 1] = h1;
            Al[r][2 * q] = l0; Al[r][2 * q + 1] = l1;
        }
        for (int idx = tid; idx < COUT * 16; idx += 256) {
            int k2 = idx / COUT;
            int n = idx % COUT;
            int kk = c * 32 + 2 * k2;
            int s = kk / CIN;
            int off = kk % CIN;
            const float* wp = W + ((size_t)s * CIN + off) * COUT + n;
            float w0 = __ldg(wp);
            float w1 = __ldg(wp + COUT);
            uint32_t h, l;
            split_pack2(w0, w1, h, l);
            Bh[n][k2] = h;
            Bl[n][k2] = l;
        }
        __syncthreads();

#pragma unroll
        for (int ks = 0; ks < 2; ks++) {
            int kq = ks * 8 + (lane & 3);
            int r0 = w * 16 + (lane >> 2);
            uint32_t ah[4], al[4];
            ah[0] = Ah[r0][kq];     ah[1] = Ah[r0 + 8][kq];
            ah[2] = Ah[r0][kq + 4]; ah[3] = Ah[r0 + 8][kq + 4];
            al[0] = Al[r0][kq];     al[1] = Al[r0 + 8][kq];
            al[2] = Al[r0][kq + 4]; al[3] = Al[r0 + 8][kq + 4];
#pragma unroll
            for (int j = 0; j < NT; j++) {
                int n = j * 8 + (lane >> 2);
                uint32_t bh[2] = { Bh[n][kq], Bh[n][kq + 4] };
                uint32_t bl[2] = { Bl[n][kq], Bl[n][kq + 4] };
                mma16816(acc[j], ah, bh);
                mma16816(acc[j], al, bh);
                mma16816(acc[j], ah, bl);
            }
        }
        __syncthreads();
    }

    int r0 = mBase + w * 16 + (lane >> 2);
#pragma unroll
    for (int j = 0; j < NT; j++) {
        int n = j * 8 + 2 * (lane & 3);
        float b0 = __ldg(&bias[n]);
        float b1 = __ldg(&bias[n + 1]);
        float2 o0 = make_float2(elu1(acc[j][0] + b0), elu1(acc[j][1] + b1));
        float2 o1 = make_float2(elu1(acc[j][2] + b0), elu1(acc[j][3] + b1));
        *(float2*)&out[(size_t)r0 * COUT + n] = o0;
        *(float2*)&out[(size_t)(r0 + 8) * COUT + n] = o1;
    }
}

// CIN=1 special case (level-1 conv1)
__global__ void k_gemm_c1(const float* __restrict__ A0, const float* __restrict__ Arest,
                          size_t slotStride, const float* __restrict__ W,
                          const float* __restrict__ bias, float* __restrict__ out, int M) {
    __shared__ float Ws[10][32];
    __shared__ float bs[32];
    int tid = threadIdx.y * 32 + threadIdx.x;
    for (int t = tid; t < 320; t += 256) Ws[t / 32][t % 32] = W[t];
    if (tid < 32) bs[tid] = bias[tid];
    __syncthreads();
    int m = blockIdx.x * 8 + threadIdx.y;
    int n = threadIdx.x;
    float acc = A0[m] * Ws[0][n];
#pragma unroll
    for (int k = 1; k < 10; k++)
        acc += Arest[(size_t)(k - 1) * slotStride + m] * Ws[k][n];
    out[(size_t)m * 32 + n] = elu1(acc + bs[n]);
}

// ---------------------------------------------------------------------------
// Fused skip-write + pooling
// ---------------------------------------------------------------------------
__global__ void k_skip_pool_next4(const float4* __restrict__ in, float4* __restrict__ skip,
                                  float4* __restrict__ pool, int Vin, int C4) {
    int t = blockIdx.x * blockDim.x + threadIdx.x;
    int F4 = BATCH * C4;
    int n = (Vin / 4) * F4;
    if (t >= n) return;
    int v4 = t / F4;
    int f = t - v4 * F4;
    int b = f / C4;
    int c = f - b * C4;
    const float4* bp = in + (size_t)(4 * v4) * F4 + f;
    float4 a0 = bp[0], a1 = bp[F4], a2 = bp[2 * F4], a3 = bp[3 * F4];
    skip[((size_t)b * Vin + 4 * v4 + 0) * C4 + c] = a0;
    skip[((size_t)b * Vin + 4 * v4 + 1) * C4 + c] = a1;
    skip[((size_t)b * Vin + 4 * v4 + 2) * C4 + c] = a2;
    skip[((size_t)b * Vin + 4 * v4 + 3) * C4 + c] = a3;
    float4 o;
    o.x = 0.25f * (a0.x + a1.x + a2.x + a3.x);
    o.y = 0.25f * (a0.y + a1.y + a2.y + a3.y);
    o.z = 0.25f * (a0.z + a1.z + a2.z + a3.z);
    o.w = 0.25f * (a0.w + a1.w + a2.w + a3.w);
    pool[t] = o;
}
__global__ void k_skip_pool_out4(const float4* __restrict__ in, float4* __restrict__ skip,
                                 float4* __restrict__ poolT, int Vin, int C4) {
    int t = blockIdx.x * blockDim.x + threadIdx.x;
    int F4 = BATCH * C4;
    int Vout = Vin / 4;
    int n = Vout * F4;
    if (t >= n) return;
    int v4 = t / F4;
    int f = t - v4 * F4;
    int b = f / C4;
    int c = f - b * C4;
    const float4* bp = in + (size_t)(4 * v4) * F4 + f;
    float4 a0 = bp[0], a1 = bp[F4], a2 = bp[2 * F4], a3 = bp[3 * F4];
    skip[((size_t)b * Vin + 4 * v4 + 0) * C4 + c] = a0;
    skip[((size_t)b * Vin + 4 * v4 + 1) * C4 + c] = a1;
    skip[((size_t)b * Vin + 4 * v4 + 2) * C4 + c] = a2;
    skip[((size_t)b * Vin + 4 * v4 + 3) * C4 + c] = a3;
    float4 o;
    o.x = 0.25f * (a0.x + a1.x + a2.x + a3.x);
    o.y = 0.25f * (a0.y + a1.y + a2.y + a3.y);
    o.z = 0.25f * (a0.z + a1.z + a2.z + a3.z);
    o.w = 0.25f * (a0.w + a1.w + a2.w + a3.w);
    poolT[((size_t)b * Vout + v4) * C4 + c] = o;
}

// ---------------------------------------------------------------------------
// Host orchestration (two-stream graph)
// ---------------------------------------------------------------------------
static inline int divUp(int a, int b) { return (a + b - 1) / b; }

struct Csr { int* rowPtr; int* cursor; int* colS; float* valS; int* orig; int* bsum; };

struct DevPtrs {
    float* cheb; float* out; float* out2;
    Csr c1, c2, c3;
};
static void get_ptrs(DevPtrs& p) {
    cudaGetSymbolAddress((void**)&p.cheb, g_cheb);
    cudaGetSymbolAddress((void**)&p.out, g_out);
    cudaGetSymbolAddress((void**)&p.out2, g_out2);
    cudaGetSymbolAddress((void**)&p.c1.rowPtr, g_rowPtr1);
    cudaGetSymbolAddress((void**)&p.c1.cursor, g_cursor1);
    cudaGetSymbolAddress((void**)&p.c1.colS, g_colS1);
    cudaGetSymbolAddress((void**)&p.c1.valS, g_valS1);
    cudaGetSymbolAddress((void**)&p.c1.orig, g_orig1);
    cudaGetSymbolAddress((void**)&p.c1.bsum, g_bsum1);
    cudaGetSymbolAddress((void**)&p.c2.rowPtr, g_rowPtr2);
    cudaGetSymbolAddress((void**)&p.c2.cursor, g_cursor2);
    cudaGetSymbolAddress((void**)&p.c2.colS, g_colS2);
    cudaGetSymbolAddress((void**)&p.c2.valS, g_valS2);
    cudaGetSymbolAddress((void**)&p.c2.orig, g_orig2);
    cudaGetSymbolAddress((void**)&p.c2.bsum, g_bsum2);
    cudaGetSymbolAddress((void**)&p.c3.rowPtr, g_rowPtr3);
    cudaGetSymbolAddress((void**)&p.c3.cursor, g_cursor3);
    cudaGetSymbolAddress((void**)&p.c3.colS, g_colS3);
    cudaGetSymbolAddress((void**)&p.c3.valS, g_valS3);
    cudaGetSymbolAddress((void**)&p.c3.orig, g_orig3);
    cudaGetSymbolAddress((void**)&p.c3.bsum, g_bsum3);
}

static void build_csr(const Csr& c, const int* rows, const int* cols, const float* vals,
                      int V, int E, cudaStream_t st) {
    k_zero_int<<<divUp(V + 1, 256), 256, 0, st>>>(c.cursor, V + 1);
    k_hist<<<divUp(E, 256), 256, 0, st>>>(rows, c.cursor, E);
    int nb = divUp(V, 1024);
    k_scan_block<<<nb, 1024, 0, st>>>(c.cursor, c.rowPtr, c.bsum, V);
    k_scan_top<<<1, 64, 0, st>>>(c.bsum, nb);
    k_scan_add<<<divUp(V + 1, 256), 256, 0, st>>>(c.rowPtr, c.cursor, c.bsum, V, E);
    k_scatter<<<divUp(E, 256), 256, 0, st>>>(rows, cols, vals, c.cursor, c.colS, c.valS, c.orig, E);
    k_rowsort<<<divUp(V, 256), 256, 0, st>>>(c.rowPtr, c.colS, c.valS, c.orig, V);
}

template <int F, int FTOT>
static void spmv_chain_off(const DevPtrs& p, const Csr& c, const float* x0base, int V,
                           int f4off, cudaStream_t st) {
    constexpr int F4 = F / 4;
    constexpr int ROWS = (F4 >= 256) ? 1 : (256 / F4);
    constexpr int F4S = FTOT / 4;
    dim3 blk(F4, ROWS);
    size_t S4 = (size_t)V * F4S;
    const float4* x0 = (const float4*)x0base + f4off;
    float4* cheb = (float4*)p.cheb + f4off;
    k_spmv4<F4, ROWS, false><<<V / ROWS, blk, 0, st>>>(c.rowPtr, c.colS, c.valS,
                                                       x0, nullptr, cheb + S4, V, F4S);
    for (int k = 2; k < 10; k++) {
        const float4* xk1 = cheb + (size_t)(k - 1) * S4;
        const float4* xk2 = (k == 2) ? x0 : (cheb + (size_t)(k - 2) * S4);
        k_spmv4<F4, ROWS, true><<<V / ROWS, blk, 0, st>>>(c.rowPtr, c.colS, c.valS,
                                                          xk1, xk2, cheb + (size_t)k * S4, V, F4S);
    }
}

extern "C" void kernel_launch(void* const* d_in, const int* in_sizes, int n_in,
                              void* d_out_v, int out_size) {
    (void)in_sizes; (void)n_in; (void)out_size;
    DevPtrs p; get_ptrs(p);

    // streams/events: host-side statics, created once (no device allocation)
    static cudaStream_t s0 = nullptr, s1 = nullptr;
    static cudaEvent_t evRoot, evT, evG1, evHB, evC2, evC3, evEnd;
    if (!s0) {
        cudaStreamCreateWithFlags(&s0, cudaStreamNonBlocking);
        cudaStreamCreateWithFlags(&s1, cudaStreamNonBlocking);
        cudaEventCreateWithFlags(&evRoot, cudaEventDisableTiming);
        cudaEventCreateWithFlags(&evT, cudaEventDisableTiming);
        cudaEventCreateWithFlags(&evG1, cudaEventDisableTiming);
        cudaEventCreateWithFlags(&evHB, cudaEventDisableTiming);
        cudaEventCreateWithFlags(&evC2, cudaEventDisableTiming);
        cudaEventCreateWithFlags(&evC3, cudaEventDisableTiming);
        cudaEventCreateWithFlags(&evEnd, cudaEventDisableTiming);
    }

    const float* x    = (const float*)d_in[0];
    const float* w1_1 = (const float*)d_in[1];
    const float* b1_1 = (const float*)d_in[2];
    const float* w2_1 = (const float*)d_in[3];
    const float* b2_1 = (const float*)d_in[4];
    const int*   rows1 = (const int*)d_in[5];
    const int*   cols1 = (const int*)d_in[6];
    const float* vals1 = (const float*)d_in[7];
    const float* w1_2 = (const float*)d_in[8];
    const float* b1_2 = (const float*)d_in[9];
    const float* w2_2 = (const float*)d_in[10];
    const float* b2_2 = (const float*)d_in[11];
    const int*   rows2 = (const int*)d_in[12];
    const int*   cols2 = (const int*)d_in[13];
    const float* vals2 = (const float*)d_in[14];
    const float* w1_3 = (const float*)d_in[15];
    const float* b1_3 = (const float*)d_in[16];
    const float* w2_3 = (const float*)d_in[17];
    const float* b2_3 = (const float*)d_in[18];
    const int*   rows3 = (const int*)d_in[19];
    const int*   cols3 = (const int*)d_in[20];
    const float* vals3 = (const float*)d_in[21];

    float* d_out = (float*)d_out_v;
    float* out_skip1 = d_out;                       // [8,49152,32]
    float* out_skip2 = d_out + (size_t)12582912;    // [8,12288,64]
    float* out_skip3 = out_skip2 + (size_t)6291456; // [8,3072,128]
    float* out_x     = out_skip3 + (size_t)3145728; // [8,768,128]

    // ---- fork from capture-origin (legacy) stream ----
    cudaEventRecord(evRoot, 0);
    cudaStreamWaitEvent(s0, evRoot, 0);
    cudaStreamWaitEvent(s1, evRoot, 0);

    // s1: input transpose (independent of CSR1)
    k_transpose_in<<<divUp(V1, 256), 256, 0, s1>>>(x, p.cheb, V1);
    cudaEventRecord(evT, s1);

    // s0: level-1 CSR, then F=8 chain + conv1 GEMM
    build_csr(p.c1, rows1, cols1, vals1, V1, E1, s0);
    cudaStreamWaitEvent(s0, evT, 0);
    spmv_chain_off<8, 8>(p, p.c1, p.cheb, V1, 0, s0);
    k_gemm_c1<<<V1 * BATCH / 8, dim3(32, 8), 0, s0>>>(
        p.cheb, p.cheb + (size_t)V1 * 8, (size_t)V1 * 8, w1_1, b1_1, p.out, V1 * BATCH);
    cudaEventRecord(evG1, s0);

    // s1: CSR builds for levels 2 and 3 (overlap with level-1 compute),
    //     then half-chain B after conv1 GEMM
    build_csr(p.c2, rows2, cols2, vals2, V2, E2, s1);
    cudaEventRecord(evC2, s1);
    build_csr(p.c3, rows3, cols3, vals3, V3, E3, s1);
    cudaEventRecord(evC3, s1);
    cudaStreamWaitEvent(s1, evG1, 0);
    spmv_chain_off<128, 256>(p, p.c1, p.out, V1, 32, s1);
    cudaEventRecord(evHB, s1);

    // s0: half-chain A, then conv2 GEMM + fused skip/pool
    spmv_chain_off<128, 256>(p, p.c1, p.out, V1, 0, s0);
    cudaStreamWaitEvent(s0, evHB, 0);
    k_gemm_mma<32, 32><<<V1 * BATCH / 128, 256, 0, s0>>>(
        p.out, p.cheb + (size_t)V1 * 256, (size_t)V1 * 256, w2_1, b2_1, p.out2);
    {
        int n2 = (V1 / 4) * BATCH * 8;
        k_skip_pool_next4<<<divUp(n2, 256), 256, 0, s0>>>(
            (const float4*)p.out2, (float4*)out_skip1, (float4*)p.cheb, V1, 8);
    }

    // ---------------- Level 2 (s0; CSR2 already built on s1) ----------------
    cudaStreamWaitEvent(s0, evC2, 0);
    spmv_chain_off<256, 256>(p, p.c2, p.cheb, V2, 0, s0);
    k_gemm_mma<32, 64><<<V2 * BATCH / 128, 256, 0, s0>>>(
        p.cheb, p.cheb + (size_t)V2 * 256, (size_t)V2 * 256, w1_2, b1_2, p.out);

    spmv_chain_off<512, 512>(p, p.c2, p.out, V2, 0, s0);
    k_gemm_mma<64, 64><<<V2 * BATCH / 128, 256, 0, s0>>>(
        p.out, p.cheb + (size_t)V2 * 512, (size_t)V2 * 512, w2_2, b2_2, p.out2);
    {
        int n2 = (V2 / 4) * BATCH * 16;
        k_skip_pool_next4<<<divUp(n2, 256), 256, 0, s0>>>(
            (const float4*)p.out2, (float4*)out_skip2, (float4*)p.cheb, V2, 16);
    }

    // ---------------- Level 3 (s0; CSR3 already built on s1) ----------------
    cudaStreamWaitEvent(s0, evC3, 0);
    spmv_chain_off<512, 512>(p, p.c3, p.cheb, V3, 0, s0);
    k_gemm_mma<64, 128><<<V3 * BATCH / 128, 256, 0, s0>>>(
        p.cheb, p.cheb + (size_t)V3 * 512, (size_t)V3 * 512, w1_3, b1_3, p.out);

    spmv_chain_off<1024, 1024>(p, p.c3, p.out, V3, 0, s0);
    k_gemm_mma<128, 128><<<V3 * BATCH / 128, 256, 0, s0>>>(
        p.out, p.cheb + (size_t)V3 * 1024, (size_t)V3 * 1024, w2_3, b2_3, p.out2);
    {
        int n2 = (V3 / 4) * BATCH * 32;
        k_skip_pool_out4<<<divUp(n2, 256), 256, 0, s0>>>(
            (const float4*)p.out2, (float4*)out_skip3, (float4*)out_x, V3, 32);
    }

    // ---- join back to capture-origin stream ----
    cudaEventRecord(evEnd, s0);
    cudaStreamWaitEvent(0, evEnd, 0);
}

// round 8
// speedup vs baseline: 3.4764x; 1.0416x over previous
#include <cuda_runtime.h>
#include <cuda_bf16.h>
#include <cstdint>
#include <cstdio>

#define BATCH 8
#define V1 49152
#define V2 12288
#define V3 3072
#define E1 393216
#define E2 98304
#define E3 24576

// Scratch (device globals; allocation-free rule)
__device__ float g_cheb[125829120];   // 10 * 49152 * 256 floats
__device__ float g_out[12582912];
__device__ float g_out2[12582912];
__device__ float g_part[12582912];    // GEMM phase-1 partial accumulator
// per-level CSR buffers (enables concurrent builds)
__device__ int   g_rowPtr1[V1 + 1];  __device__ int g_cursor1[V1 + 1];
__device__ int   g_colS1[E1];        __device__ float g_valS1[E1];
__device__ int   g_orig1[E1];        __device__ int g_bsum1[64];
__device__ int   g_rowPtr2[V2 + 1];  __device__ int g_cursor2[V2 + 1];
__device__ int   g_colS2[E2];        __device__ float g_valS2[E2];
__device__ int   g_orig2[E2];        __device__ int g_bsum2[64];
__device__ int   g_rowPtr3[V3 + 1];  __device__ int g_cursor3[V3 + 1];
__device__ int   g_colS3[E3];        __device__ float g_valS3[E3];
__device__ int   g_orig3[E3];        __device__ int g_bsum3[64];

__device__ __forceinline__ float elu1(float x) { return x > 0.f ? x : expm1f(x); }

// ---------------------------------------------------------------------------
// Utility kernels
// ---------------------------------------------------------------------------
__global__ void k_zero_int(int* p, int n) {
    int i = blockIdx.x * blockDim.x + threadIdx.x;
    if (i < n) p[i] = 0;
}
__global__ void k_transpose_in(const float* __restrict__ x, float* __restrict__ out, int V) {
    int v = blockIdx.x * blockDim.x + threadIdx.x;
    if (v < V) {
#pragma unroll
        for (int b = 0; b < BATCH; b++)
            out[(size_t)v * BATCH + b] = x[(size_t)b * V + v];
    }
}

// ---------------------------------------------------------------------------
// CSR build (deterministic)
// ---------------------------------------------------------------------------
__global__ void k_hist(const int* __restrict__ rows, int* cnt, int E) {
    int e = blockIdx.x * blockDim.x + threadIdx.x;
    if (e < E) atomicAdd(&cnt[rows[e]], 1);
}
__global__ void k_scan_block(const int* __restrict__ cnt, int* __restrict__ outEx,
                             int* __restrict__ bsum, int V) {
    __shared__ int s[1024];
    int tid = threadIdx.x;
    int i = blockIdx.x * 1024 + tid;
    int v = (i < V) ? cnt[i] : 0;
    s[tid] = v;
    __syncthreads();
    for (int off = 1; off < 1024; off <<= 1) {
        int t = 0;
        if (tid >= off) t = s[tid - off];
        __syncthreads();
        s[tid] += t;
        __syncthreads();
    }
    if (i < V) outEx[i] = s[tid] - v;
    if (tid == 1023) bsum[blockIdx.x] = s[1023];
}
__global__ void k_scan_top(int* bsum, int nb) {
    __shared__ int s[64];
    int t = threadIdx.x;
    int v = (t < nb) ? bsum[t] : 0;
    s[t] = v;
    __syncthreads();
    for (int off = 1; off < 64; off <<= 1) {
        int x = (t >= off) ? s[t - off] : 0;
        __syncthreads();
        s[t] += x;
        __syncthreads();
    }
    if (t < nb) bsum[t] = s[t] - v;
}
__global__ void k_scan_add(int* rowPtr, int* cursor, const int* __restrict__ bsum,
                           int V, int E) {
    int i = blockIdx.x * blockDim.x + threadIdx.x;
    if (i < V) {
        int val = rowPtr[i] + bsum[i >> 10];
        rowPtr[i] = val;
        cursor[i] = val;
    }
    if (i == 0) rowPtr[V] = E;
}
__global__ void k_scatter(const int* __restrict__ rows, const int* __restrict__ cols,
                          const float* __restrict__ vals, int* cursor,
                          int* colS, float* valS, int* orig, int E) {
    int e = blockIdx.x * blockDim.x + threadIdx.x;
    if (e < E) {
        int r = rows[e];
        int pos = atomicAdd(&cursor[r], 1);
        colS[pos] = cols[e];
        valS[pos] = vals[e];
        orig[pos] = e;
    }
}
__global__ void k_rowsort(const int* __restrict__ rowPtr, int* colS, float* valS, int* orig, int V) {
    int v = blockIdx.x * blockDim.x + threadIdx.x;
    if (v >= V) return;
    int s = rowPtr[v], e = rowPtr[v + 1];
    for (int i = s + 1; i < e; i++) {
        int ko = orig[i]; int kc = colS[i]; float kv = valS[i];
        int j = i - 1;
        while (j >= s && orig[j] > ko) {
            orig[j + 1] = orig[j]; colS[j + 1] = colS[j]; valS[j + 1] = valS[j];
            j--;
        }
        orig[j + 1] = ko; colS[j + 1] = kc; valS[j + 1] = kv;
    }
}

// ---------------------------------------------------------------------------
// SpMV (float4, 4-edge unrolled, runtime row-stride F4S for feature-split)
// ---------------------------------------------------------------------------
template <int F4, int ROWS, bool HASPREV>
__global__ void k_spmv4(const int* __restrict__ rowPtr, const int* __restrict__ colS,
                        const float* __restrict__ valS,
                        const float4* __restrict__ xin, const float4* __restrict__ xprev,
                        float4* __restrict__ y, int V, int F4S) {
    int f = threadIdx.x;
    int v = blockIdx.x * ROWS + threadIdx.y;
    int s = rowPtr[v], e = rowPtr[v + 1];
    float4 acc = make_float4(0.f, 0.f, 0.f, 0.f);
    int i = s;
    for (; i + 4 <= e; i += 4) {
        int c0 = colS[i];     float w0 = valS[i];
        int c1 = colS[i + 1]; float w1 = valS[i + 1];
        int c2 = colS[i + 2]; float w2 = valS[i + 2];
        int c3 = colS[i + 3]; float w3 = valS[i + 3];
        float4 g0 = xin[(size_t)c0 * F4S + f];
        float4 g1 = xin[(size_t)c1 * F4S + f];
        float4 g2 = xin[(size_t)c2 * F4S + f];
        float4 g3 = xin[(size_t)c3 * F4S + f];
        acc.x += w0 * g0.x; acc.y += w0 * g0.y; acc.z += w0 * g0.z; acc.w += w0 * g0.w;
        acc.x += w1 * g1.x; acc.y += w1 * g1.y; acc.z += w1 * g1.z; acc.w += w1 * g1.w;
        acc.x += w2 * g2.x; acc.y += w2 * g2.y; acc.z += w2 * g2.z; acc.w += w2 * g2.w;
        acc.x += w3 * g3.x; acc.y += w3 * g3.y; acc.z += w3 * g3.z; acc.w += w3 * g3.w;
    }
    for (; i < e; i++) {
        int c0 = colS[i]; float w0 = valS[i];
        float4 g0 = xin[(size_t)c0 * F4S + f];
        acc.x += w0 * g0.x; acc.y += w0 * g0.y; acc.z += w0 * g0.z; acc.w += w0 * g0.w;
    }
    if (HASPREV) {
        float4 pv = xprev[(size_t)v * F4S + f];
        acc.x = 2.f * acc.x - pv.x; acc.y = 2.f * acc.y - pv.y;
        acc.z = 2.f * acc.z - pv.z; acc.w = 2.f * acc.w - pv.w;
    }
    y[(size_t)v * F4S + f] = acc;
}

// ---------------------------------------------------------------------------
// mma.sync bf16x3 Chebyshev GEMM, two-phase (chunk range [c0, c1))
// PHASE 0: write raw fp32 partial. PHASE 1: add partial + bias + ELU.
// ---------------------------------------------------------------------------
__device__ __forceinline__ void mma16816(float* d, const uint32_t* a, const uint32_t* b) {
    asm volatile(
        "mma.sync.aligned.m16n8k16.row.col.f32.bf16.bf16.f32 "
        "{%0,%1,%2,%3}, {%4,%5,%6,%7}, {%8,%9}, {%0,%1,%2,%3};\n"
        : "+f"(d[0]), "+f"(d[1]), "+f"(d[2]), "+f"(d[3])
        : "r"(a[0]), "r"(a[1]), "r"(a[2]), "r"(a[3]), "r"(b[0]), "r"(b[1]));
}

__device__ __forceinline__ void split_pack2(float x0, float x1, uint32_t& hi, uint32_t& lo) {
    __nv_bfloat16 h0 = __float2bfloat16_rn(x0);
    __nv_bfloat16 h1 = __float2bfloat16_rn(x1);
    __nv_bfloat16 l0 = __float2bfloat16_rn(x0 - __bfloat162float(h0));
    __nv_bfloat16 l1 = __float2bfloat16_rn(x1 - __bfloat162float(h1));
    __nv_bfloat162 hv(h0, h1), lv(l0, l1);
    hi = *(uint32_t*)&hv;
    lo = *(uint32_t*)&lv;
}

template <int CIN, int COUT, int PHASE>
__global__ __launch_bounds__(256)
void k_gemm_mma(const float* __restrict__ A0, const float* __restrict__ Arest,
                size_t slotStride, const float* __restrict__ W,
                const float* __restrict__ bias,
                float* __restrict__ partial, float* __restrict__ out,
                int c0, int c1) {
    constexpr int NT = COUT / 8;

    __shared__ uint32_t Ah[128][17];
    __shared__ uint32_t Al[128][17];
    __shared__ uint32_t Bh[COUT][17];
    __shared__ uint32_t Bl[COUT][17];

    int tid = threadIdx.x;
    int lane = tid & 31;
    int w = tid >> 5;
    int mBase = blockIdx.x * 128;

    float acc[NT][4];
#pragma unroll
    for (int j = 0; j < NT; j++)
#pragma unroll
        for (int q = 0; q < 4; q++) acc[j][q] = 0.f;

    for (int c = c0; c < c1; c++) {
#pragma unroll
        for (int it = 0; it < 4; it++) {
            int idx = it * 256 + tid;
            int r = idx >> 3;
            int q = idx & 7;
            int kk = c * 32 + q * 4;
            int s = kk / CIN;
            int off = kk % CIN;
            const float* src = ((s == 0) ? A0 : (Arest + (size_t)(s - 1) * slotStride))
                               + (size_t)(mBase + r) * CIN + off;
            float4 a = *(const float4*)src;
            uint32_t h0, l0, h1, l1;
            split_pack2(a.x, a.y, h0, l0);
            split_pack2(a.z, a.w, h1, l1);
            Ah[r][2 * q] = h0; Ah[r][2 * q + 1] = h1;
            Al[r][2 * q] = l0; Al[r][2 * q + 1] = l1;
        }
        for (int idx = tid; idx < COUT * 16; idx += 256) {
            int k2 = idx / COUT;
            int n = idx % COUT;
            int kk = c * 32 + 2 * k2;
            int s = kk / CIN;
            int off = kk % CIN;
            const float* wp = W + ((size_t)s * CIN + off) * COUT + n;
            float w0 = __ldg(wp);
            float w1 = __ldg(wp + COUT);
            uint32_t h, l;
            split_pack2(w0, w1, h, l);
            Bh[n][k2] = h;
            Bl[n][k2] = l;
        }
        __syncthreads();

#pragma unroll
        for (int ks = 0; ks < 2; ks++) {
            int kq = ks * 8 + (lane & 3);
            int r0 = w * 16 + (lane >> 2);
            uint32_t ah[4], al[4];
            ah[0] = Ah[r0][kq];     ah[1] = Ah[r0 + 8][kq];
            ah[2] = Ah[r0][kq + 4]; ah[3] = Ah[r0 + 8][kq + 4];
            al[0] = Al[r0][kq];     al[1] = Al[r0 + 8][kq];
            al[2] = Al[r0][kq + 4]; al[3] = Al[r0 + 8][kq + 4];
#pragma unroll
            for (int j = 0; j < NT; j++) {
                int n = j * 8 + (lane >> 2);
                uint32_t bh[2] = { Bh[n][kq], Bh[n][kq + 4] };
                uint32_t bl[2] = { Bl[n][kq], Bl[n][kq + 4] };
                mma16816(acc[j], ah, bh);
                mma16816(acc[j], al, bh);
                mma16816(acc[j], ah, bl);
            }
        }
        __syncthreads();
    }

    int r0 = mBase + w * 16 + (lane >> 2);
#pragma unroll
    for (int j = 0; j < NT; j++) {
        int n = j * 8 + 2 * (lane & 3);
        if (PHASE == 0) {
            *(float2*)&partial[(size_t)r0 * COUT + n] = make_float2(acc[j][0], acc[j][1]);
            *(float2*)&partial[(size_t)(r0 + 8) * COUT + n] = make_float2(acc[j][2], acc[j][3]);
        } else {
            float2 q0 = *(const float2*)&partial[(size_t)r0 * COUT + n];
            float2 q1 = *(const float2*)&partial[(size_t)(r0 + 8) * COUT + n];
            float b0 = __ldg(&bias[n]);
            float b1 = __ldg(&bias[n + 1]);
            float2 o0 = make_float2(elu1(acc[j][0] + q0.x + b0), elu1(acc[j][1] + q0.y + b1));
            float2 o1 = make_float2(elu1(acc[j][2] + q1.x + b0), elu1(acc[j][3] + q1.y + b1));
            *(float2*)&out[(size_t)r0 * COUT + n] = o0;
            *(float2*)&out[(size_t)(r0 + 8) * COUT + n] = o1;
        }
    }
}

// CIN=1 special case (level-1 conv1)
__global__ void k_gemm_c1(const float* __restrict__ A0, const float* __restrict__ Arest,
                          size_t slotStride, const float* __restrict__ W,
                          const float* __restrict__ bias, float* __restrict__ out, int M) {
    __shared__ float Ws[10][32];
    __shared__ float bs[32];
    int tid = threadIdx.y * 32 + threadIdx.x;
    for (int t = tid; t < 320; t += 256) Ws[t / 32][t % 32] = W[t];
    if (tid < 32) bs[tid] = bias[tid];
    __syncthreads();
    int m = blockIdx.x * 8 + threadIdx.y;
    int n = threadIdx.x;
    float acc = A0[m] * Ws[0][n];
#pragma unroll
    for (int k = 1; k < 10; k++)
        acc += Arest[(size_t)(k - 1) * slotStride + m] * Ws[k][n];
    out[(size_t)m * 32 + n] = elu1(acc + bs[n]);
}

// ---------------------------------------------------------------------------
// Fused skip-write + pooling
// ---------------------------------------------------------------------------
__global__ void k_skip_pool_next4(const float4* __restrict__ in, float4* __restrict__ skip,
                                  float4* __restrict__ pool, int Vin, int C4) {
    int t = blockIdx.x * blockDim.x + threadIdx.x;
    int F4 = BATCH * C4;
    int n = (Vin / 4) * F4;
    if (t >= n) return;
    int v4 = t / F4;
    int f = t - v4 * F4;
    int b = f / C4;
    int c = f - b * C4;
    const float4* bp = in + (size_t)(4 * v4) * F4 + f;
    float4 a0 = bp[0], a1 = bp[F4], a2 = bp[2 * F4], a3 = bp[3 * F4];
    skip[((size_t)b * Vin + 4 * v4 + 0) * C4 + c] = a0;
    skip[((size_t)b * Vin + 4 * v4 + 1) * C4 + c] = a1;
    skip[((size_t)b * Vin + 4 * v4 + 2) * C4 + c] = a2;
    skip[((size_t)b * Vin + 4 * v4 + 3) * C4 + c] = a3;
    float4 o;
    o.x = 0.25f * (a0.x + a1.x + a2.x + a3.x);
    o.y = 0.25f * (a0.y + a1.y + a2.y + a3.y);
    o.z = 0.25f * (a0.z + a1.z + a2.z + a3.z);
    o.w = 0.25f * (a0.w + a1.w + a2.w + a3.w);
    pool[t] = o;
}
__global__ void k_skip_pool_out4(const float4* __restrict__ in, float4* __restrict__ skip,
                                 float4* __restrict__ poolT, int Vin, int C4) {
    int t = blockIdx.x * blockDim.x + threadIdx.x;
    int F4 = BATCH * C4;
    int Vout = Vin / 4;
    int n = Vout * F4;
    if (t >= n) return;
    int v4 = t / F4;
    int f = t - v4 * F4;
    int b = f / C4;
    int c = f - b * C4;
    const float4* bp = in + (size_t)(4 * v4) * F4 + f;
    float4 a0 = bp[0], a1 = bp[F4], a2 = bp[2 * F4], a3 = bp[3 * F4];
    skip[((size_t)b * Vin + 4 * v4 + 0) * C4 + c] = a0;
    skip[((size_t)b * Vin + 4 * v4 + 1) * C4 + c] = a1;
    skip[((size_t)b * Vin + 4 * v4 + 2) * C4 + c] = a2;
    skip[((size_t)b * Vin + 4 * v4 + 3) * C4 + c] = a3;
    float4 o;
    o.x = 0.25f * (a0.x + a1.x + a2.x + a3.x);
    o.y = 0.25f * (a0.y + a1.y + a2.y + a3.y);
    o.z = 0.25f * (a0.z + a1.z + a2.z + a3.z);
    o.w = 0.25f * (a0.w + a1.w + a2.w + a3.w);
    poolT[((size_t)b * Vout + v4) * C4 + c] = o;
}

// ---------------------------------------------------------------------------
// Host orchestration (two-stream graph with hidden CSR + hidden GEMM phase-1)
// ---------------------------------------------------------------------------
static inline int divUp(int a, int b) { return (a + b - 1) / b; }

struct Csr { int* rowPtr; int* cursor; int* colS; float* valS; int* orig; int* bsum; };

struct DevPtrs {
    float* cheb; float* out; float* out2; float* part;
    Csr c1, c2, c3;
};
static void get_ptrs(DevPtrs& p) {
    cudaGetSymbolAddress((void**)&p.cheb, g_cheb);
    cudaGetSymbolAddress((void**)&p.out, g_out);
    cudaGetSymbolAddress((void**)&p.out2, g_out2);
    cudaGetSymbolAddress((void**)&p.part, g_part);
    cudaGetSymbolAddress((void**)&p.c1.rowPtr, g_rowPtr1);
    cudaGetSymbolAddress((void**)&p.c1.cursor, g_cursor1);
    cudaGetSymbolAddress((void**)&p.c1.colS, g_colS1);
    cudaGetSymbolAddress((void**)&p.c1.valS, g_valS1);
    cudaGetSymbolAddress((void**)&p.c1.orig, g_orig1);
    cudaGetSymbolAddress((void**)&p.c1.bsum, g_bsum1);
    cudaGetSymbolAddress((void**)&p.c2.rowPtr, g_rowPtr2);
    cudaGetSymbolAddress((void**)&p.c2.cursor, g_cursor2);
    cudaGetSymbolAddress((void**)&p.c2.colS, g_colS2);
    cudaGetSymbolAddress((void**)&p.c2.valS, g_valS2);
    cudaGetSymbolAddress((void**)&p.c2.orig, g_orig2);
    cudaGetSymbolAddress((void**)&p.c2.bsum, g_bsum2);
    cudaGetSymbolAddress((void**)&p.c3.rowPtr, g_rowPtr3);
    cudaGetSymbolAddress((void**)&p.c3.cursor, g_cursor3);
    cudaGetSymbolAddress((void**)&p.c3.colS, g_colS3);
    cudaGetSymbolAddress((void**)&p.c3.valS, g_valS3);
    cudaGetSymbolAddress((void**)&p.c3.orig, g_orig3);
    cudaGetSymbolAddress((void**)&p.c3.bsum, g_bsum3);
}

static void build_csr(const Csr& c, const int* rows, const int* cols, const float* vals,
                      int V, int E, cudaStream_t st) {
    k_zero_int<<<divUp(V + 1, 256), 256, 0, st>>>(c.cursor, V + 1);
    k_hist<<<divUp(E, 256), 256, 0, st>>>(rows, c.cursor, E);
    int nb = divUp(V, 1024);
    k_scan_block<<<nb, 1024, 0, st>>>(c.cursor, c.rowPtr, c.bsum, V);
    k_scan_top<<<1, 64, 0, st>>>(c.bsum, nb);
    k_scan_add<<<divUp(V + 1, 256), 256, 0, st>>>(c.rowPtr, c.cursor, c.bsum, V, E);
    k_scatter<<<divUp(E, 256), 256, 0, st>>>(rows, cols, vals, c.cursor, c.colS, c.valS, c.orig, E);
    k_rowsort<<<divUp(V, 256), 256, 0, st>>>(c.rowPtr, c.colS, c.valS, c.orig, V);
}

// Chebyshev chain; optionally records evMid after the pass that completes slot 4.
template <int F, int FTOT>
static void spmv_chain_off(const DevPtrs& p, const Csr& c, const float* x0base, int V,
                           int f4off, cudaStream_t st, cudaEvent_t evMid = nullptr) {
    constexpr int F4 = F / 4;
    constexpr int ROWS = (F4 >= 256) ? 1 : (256 / F4);
    constexpr int F4S = FTOT / 4;
    dim3 blk(F4, ROWS);
    size_t S4 = (size_t)V * F4S;
    const float4* x0 = (const float4*)x0base + f4off;
    float4* cheb = (float4*)p.cheb + f4off;
    k_spmv4<F4, ROWS, false><<<V / ROWS, blk, 0, st>>>(c.rowPtr, c.colS, c.valS,
                                                       x0, nullptr, cheb + S4, V, F4S);
    for (int k = 2; k < 10; k++) {
        const float4* xk1 = cheb + (size_t)(k - 1) * S4;
        const float4* xk2 = (k == 2) ? x0 : (cheb + (size_t)(k - 2) * S4);
        k_spmv4<F4, ROWS, true><<<V / ROWS, blk, 0, st>>>(c.rowPtr, c.colS, c.valS,
                                                          xk1, xk2, cheb + (size_t)k * S4, V, F4S);
        if (evMid && k == 4) cudaEventRecord(evMid, st);
    }
}

extern "C" void kernel_launch(void* const* d_in, const int* in_sizes, int n_in,
                              void* d_out_v, int out_size) {
    (void)in_sizes; (void)n_in; (void)out_size;
    DevPtrs p; get_ptrs(p);

    static cudaStream_t s0 = nullptr, s1 = nullptr;
    static cudaEvent_t evRoot, evT, evC2, evC3, evEnd;
    static cudaEvent_t evMid[5], evP1[5];
    if (!s0) {
        cudaStreamCreateWithFlags(&s0, cudaStreamNonBlocking);
        cudaStreamCreateWithFlags(&s1, cudaStreamNonBlocking);
        cudaEventCreateWithFlags(&evRoot, cudaEventDisableTiming);
        cudaEventCreateWithFlags(&evT, cudaEventDisableTiming);
        cudaEventCreateWithFlags(&evC2, cudaEventDisableTiming);
        cudaEventCreateWithFlags(&evC3, cudaEventDisableTiming);
        cudaEventCreateWithFlags(&evEnd, cudaEventDisableTiming);
        for (int i = 0; i < 5; i++) {
            cudaEventCreateWithFlags(&evMid[i], cudaEventDisableTiming);
            cudaEventCreateWithFlags(&evP1[i], cudaEventDisableTiming);
        }
    }

    const float* x    = (const float*)d_in[0];
    const float* w1_1 = (const float*)d_in[1];
    const float* b1_1 = (const float*)d_in[2];
    const float* w2_1 = (const float*)d_in[3];
    const float* b2_1 = (const float*)d_in[4];
    const int*   rows1 = (const int*)d_in[5];
    const int*   cols1 = (const int*)d_in[6];
    const float* vals1 = (const float*)d_in[7];
    const float* w1_2 = (const float*)d_in[8];
    const float* b1_2 = (const float*)d_in[9];
    const float* w2_2 = (const float*)d_in[10];
    const float* b2_2 = (const float*)d_in[11];
    const int*   rows2 = (const int*)d_in[12];
    const int*   cols2 = (const int*)d_in[13];
    const float* vals2 = (const float*)d_in[14];
    const float* w1_3 = (const float*)d_in[15];
    const float* b1_3 = (const float*)d_in[16];
    const float* w2_3 = (const float*)d_in[17];
    const float* b2_3 = (const float*)d_in[18];
    const int*   rows3 = (const int*)d_in[19];
    const int*   cols3 = (const int*)d_in[20];
    const float* vals3 = (const float*)d_in[21];

    float* d_out = (float*)d_out_v;
    float* out_skip1 = d_out;                       // [8,49152,32]
    float* out_skip2 = d_out + (size_t)12582912;    // [8,12288,64]
    float* out_skip3 = out_skip2 + (size_t)6291456; // [8,3072,128]
    float* out_x     = out_skip3 + (size_t)3145728; // [8,768,128]

    // ---- fork ----
    cudaEventRecord(evRoot, 0);
    cudaStreamWaitEvent(s0, evRoot, 0);
    cudaStreamWaitEvent(s1, evRoot, 0);

    // s1: input transpose, then CSR builds for levels 2/3 (hidden behind level-1)
    k_transpose_in<<<divUp(V1, 256), 256, 0, s1>>>(x, p.cheb, V1);
    cudaEventRecord(evT, s1);
    build_csr(p.c2, rows2, cols2, vals2, V2, E2, s1);
    cudaEventRecord(evC2, s1);
    build_csr(p.c3, rows3, cols3, vals3, V3, E3, s1);
    cudaEventRecord(evC3, s1);

    // s0: level-1 CSR, F=8 chain, conv1 GEMM
    build_csr(p.c1, rows1, cols1, vals1, V1, E1, s0);
    cudaStreamWaitEvent(s0, evT, 0);
    spmv_chain_off<8, 8>(p, p.c1, p.cheb, V1, 0, s0);
    k_gemm_c1<<<V1 * BATCH / 8, dim3(32, 8), 0, s0>>>(
        p.cheb, p.cheb + (size_t)V1 * 8, (size_t)V1 * 8, w1_1, b1_1, p.out, V1 * BATCH);

    // level-1 conv2: SERIAL half-chains (L2 residency), evMid after half-B pass 4
    spmv_chain_off<128, 256>(p, p.c1, p.out, V1, 0, s0);
    spmv_chain_off<128, 256>(p, p.c1, p.out, V1, 32, s0, evMid[0]);
    cudaStreamWaitEvent(s1, evMid[0], 0);
    k_gemm_mma<32, 32, 0><<<V1 * BATCH / 128, 256, 0, s1>>>(
        p.out, p.cheb + (size_t)V1 * 256, (size_t)V1 * 256, w2_1, b2_1, p.part, nullptr, 0, 5);
    cudaEventRecord(evP1[0], s1);
    cudaStreamWaitEvent(s0, evP1[0], 0);
    k_gemm_mma<32, 32, 1><<<V1 * BATCH / 128, 256, 0, s0>>>(
        p.out, p.cheb + (size_t)V1 * 256, (size_t)V1 * 256, w2_1, b2_1, p.part, p.out2, 5, 10);
    {
        int n2 = (V1 / 4) * BATCH * 8;
        k_skip_pool_next4<<<divUp(n2, 256), 256, 0, s0>>>(
            (const float4*)p.out2, (float4*)out_skip1, (float4*)p.cheb, V1, 8);
    }

    // ---------------- Level 2 ----------------
    cudaStreamWaitEvent(s0, evC2, 0);
    spmv_chain_off<256, 256>(p, p.c2, p.cheb, V2, 0, s0, evMid[1]);
    cudaStreamWaitEvent(s1, evMid[1], 0);
    k_gemm_mma<32, 64, 0><<<V2 * BATCH / 128, 256, 0, s1>>>(
        p.cheb, p.cheb + (size_t)V2 * 256, (size_t)V2 * 256, w1_2, b1_2, p.part, nullptr, 0, 5);
    cudaEventRecord(evP1[1], s1);
    cudaStreamWaitEvent(s0, evP1[1], 0);
    k_gemm_mma<32, 64, 1><<<V2 * BATCH / 128, 256, 0, s0>>>(
        p.cheb, p.cheb + (size_t)V2 * 256, (size_t)V2 * 256, w1_2, b1_2, p.part, p.out, 5, 10);

    spmv_chain_off<512, 512>(p, p.c2, p.out, V2, 0, s0, evMid[2]);
    cudaStreamWaitEvent(s1, evMid[2], 0);
    k_gemm_mma<64, 64, 0><<<V2 * BATCH / 128, 256, 0, s1>>>(
        p.out, p.cheb + (size_t)V2 * 512, (size_t)V2 * 512, w2_2, b2_2, p.part, nullptr, 0, 10);
    cudaEventRecord(evP1[2], s1);
    cudaStreamWaitEvent(s0, evP1[2], 0);
    k_gemm_mma<64, 64, 1><<<V2 * BATCH / 128, 256, 0, s0>>>(
        p.out, p.cheb + (size_t)V2 * 512, (size_t)V2 * 512, w2_2, b2_2, p.part, p.out2, 10, 20);
    {
        int n2 = (V2 / 4) * BATCH * 16;
        k_skip_pool_next4<<<divUp(n2, 256), 256, 0, s0>>>(
            (const float4*)p.out2, (float4*)out_skip2, (float4*)p.cheb, V2, 16);
    }

    // ---------------- Level 3 ----------------
    cudaStreamWaitEvent(s0, evC3, 0);
    spmv_chain_off<512, 512>(p, p.c3, p.cheb, V3, 0, s0, evMid[3]);
    cudaStreamWaitEvent(s1, evMid[3], 0);
    k_gemm_mma<64, 128, 0><<<V3 * BATCH / 128, 256, 0, s1>>>(
        p.cheb, p.cheb + (size_t)V3 * 512, (size_t)V3 * 512, w1_3, b1_3, p.part, nullptr, 0, 10);
    cudaEventRecord(evP1[3], s1);
    cudaStreamWaitEvent(s0, evP1[3], 0);
    k_gemm_mma<64, 128, 1><<<V3 * BATCH / 128, 256, 0, s0>>>(
        p.cheb, p.cheb + (size_t)V3 * 512, (size_t)V3 * 512, w1_3, b1_3, p.part, p.out, 10, 20);

    spmv_chain_off<1024, 1024>(p, p.c3, p.out, V3, 0, s0, evMid[4]);
    cudaStreamWaitEvent(s1, evMid[4], 0);
    k_gemm_mma<128, 128, 0><<<V3 * BATCH / 128, 256, 0, s1>>>(
        p.out, p.cheb + (size_t)V3 * 1024, (size_t)V3 * 1024, w2_3, b2_3, p.part, nullptr, 0, 20);
    cudaEventRecord(evP1[4], s1);
    cudaStreamWaitEvent(s0, evP1[4], 0);
    k_gemm_mma<128, 128, 1><<<V3 * BATCH / 128, 256, 0, s0>>>(
        p.out, p.cheb + (size_t)V3 * 1024, (size_t)V3 * 1024, w2_3, b2_3, p.part, p.out2, 20, 40);
    {
        int n2 = (V3 / 4) * BATCH * 32;
        k_skip_pool_out4<<<divUp(n2, 256), 256, 0, s0>>>(
            (const float4*)p.out2, (float4*)out_skip3, (float4*)out_x, V3, 32);
    }

    // ---- join ----
    cudaEventRecord(evEnd, s0);
    cudaStreamWaitEvent(0, evEnd, 0);
}

// round 13
// speedup vs baseline: 3.4942x; 1.0051x over previous
#include <cuda_runtime.h>
#include <cuda_bf16.h>
#include <cuda_fp16.h>
#include <cstdint>

#define BATCH 8
#define V1 49152
#define V2 12288
#define V3 3072
#define E1 393216
#define E2 98304
#define E3 24576

// Scratch (device globals; allocation-free rule)
__device__ float g_cheb[125829120];   // fp16 cheb slots live here (reinterpreted)
__device__ float g_out[12582912];     // rotating fp32 buffer b0
__device__ float g_out2[12582912];    // rotating fp32 buffer b1
__device__ float g_part[12582912];    // GEMM phase-1 partial (b2)
// per-level CSR buffers
__device__ int   g_rowPtr1[V1 + 1];  __device__ int g_cursor1[V1 + 1];
__device__ int   g_colS1[E1];        __device__ float g_valS1[E1];
__device__ int   g_orig1[E1];        __device__ int g_bsum1[64];
__device__ int   g_rowPtr2[V2 + 1];  __device__ int g_cursor2[V2 + 1];
__device__ int   g_colS2[E2];        __device__ float g_valS2[E2];
__device__ int   g_orig2[E2];        __device__ int g_bsum2[64];
__device__ int   g_rowPtr3[V3 + 1];  __device__ int g_cursor3[V3 + 1];
__device__ int   g_colS3[E3];        __device__ float g_valS3[E3];
__device__ int   g_orig3[E3];        __device__ int g_bsum3[64];

__device__ __forceinline__ float elu1(float x) { return x > 0.f ? x : expm1f(x); }

__device__ __forceinline__ void h8_unpack(uint4 u, float* o) {
    float2 a = __half22float2(*(__half2*)&u.x);
    float2 b = __half22float2(*(__half2*)&u.y);
    float2 c = __half22float2(*(__half2*)&u.z);
    float2 d = __half22float2(*(__half2*)&u.w);
    o[0] = a.x; o[1] = a.y; o[2] = b.x; o[3] = b.y;
    o[4] = c.x; o[5] = c.y; o[6] = d.x; o[7] = d.y;
}
__device__ __forceinline__ uint4 h8_pack(const float* a) {
    __half2 h0 = __floats2half2_rn(a[0], a[1]);
    __half2 h1 = __floats2half2_rn(a[2], a[3]);
    __half2 h2 = __floats2half2_rn(a[4], a[5]);
    __half2 h3 = __floats2half2_rn(a[6], a[7]);
    uint4 u;
    u.x = *(uint32_t*)&h0; u.y = *(uint32_t*)&h1;
    u.z = *(uint32_t*)&h2; u.w = *(uint32_t*)&h3;
    return u;
}

// ---------------------------------------------------------------------------
// Utility kernels
// ---------------------------------------------------------------------------
__global__ void k_zero_int(int* p, int n) {
    int i = blockIdx.x * blockDim.x + threadIdx.x;
    if (i < n) p[i] = 0;
}
__global__ void k_transpose_in(const float* __restrict__ x, float* __restrict__ out, int V) {
    int v = blockIdx.x * blockDim.x + threadIdx.x;
    if (v < V) {
#pragma unroll
        for (int b = 0; b < BATCH; b++)
            out[(size_t)v * BATCH + b] = x[(size_t)b * V + v];
    }
}

// ---------------------------------------------------------------------------
// CSR build (deterministic)
// ---------------------------------------------------------------------------
__global__ void k_hist(const int* __restrict__ rows, int* cnt, int E) {
    int e = blockIdx.x * blockDim.x + threadIdx.x;
    if (e < E) atomicAdd(&cnt[rows[e]], 1);
}
__global__ void k_scan_block(const int* __restrict__ cnt, int* __restrict__ outEx,
                             int* __restrict__ bsum, int V) {
    __shared__ int s[1024];
    int tid = threadIdx.x;
    int i = blockIdx.x * 1024 + tid;
    int v = (i < V) ? cnt[i] : 0;
    s[tid] = v;
    __syncthreads();
    for (int off = 1; off < 1024; off <<= 1) {
        int t = 0;
        if (tid >= off) t = s[tid - off];
        __syncthreads();
        s[tid] += t;
        __syncthreads();
    }
    if (i < V) outEx[i] = s[tid] - v;
    if (tid == 1023) bsum[blockIdx.x] = s[1023];
}
__global__ void k_scan_top(int* bsum, int nb) {
    __shared__ int s[64];
    int t = threadIdx.x;
    int v = (t < nb) ? bsum[t] : 0;
    s[t] = v;
    __syncthreads();
    for (int off = 1; off < 64; off <<= 1) {
        int x = (t >= off) ? s[t - off] : 0;
        __syncthreads();
        s[t] += x;
        __syncthreads();
    }
    if (t < nb) bsum[t] = s[t] - v;
}
__global__ void k_scan_add(int* rowPtr, int* cursor, const int* __restrict__ bsum,
                           int V, int E) {
    int i = blockIdx.x * blockDim.x + threadIdx.x;
    if (i < V) {
        int val = rowPtr[i] + bsum[i >> 10];
        rowPtr[i] = val;
        cursor[i] = val;
    }
    if (i == 0) rowPtr[V] = E;
}
__global__ void k_scatter(const int* __restrict__ rows, const int* __restrict__ cols,
                          const float* __restrict__ vals, int* cursor,
                          int* colS, float* valS, int* orig, int E) {
    int e = blockIdx.x * blockDim.x + threadIdx.x;
    if (e < E) {
        int r = rows[e];
        int pos = atomicAdd(&cursor[r], 1);
        colS[pos] = cols[e];
        valS[pos] = vals[e];
        orig[pos] = e;
    }
}
__global__ void k_rowsort(const int* __restrict__ rowPtr, int* colS, float* valS, int* orig, int V) {
    int v = blockIdx.x * blockDim.x + threadIdx.x;
    if (v >= V) return;
    int s = rowPtr[v], e = rowPtr[v + 1];
    for (int i = s + 1; i < e; i++) {
        int ko = orig[i]; int kc = colS[i]; float kv = valS[i];
        int j = i - 1;
        while (j >= s && orig[j] > ko) {
            orig[j + 1] = orig[j]; colS[j + 1] = colS[j]; valS[j + 1] = valS[j];
            j--;
        }
        orig[j + 1] = ko; colS[j + 1] = kc; valS[j + 1] = kv;
    }
}

// ---------------------------------------------------------------------------
// SpMV with fp16 state storage. Thread handles 8 features (one uint4 group).
// PREV: 0 none, 1 fp32, 2 fp16.  IN32: gather source is fp32 (pass 1 only).
// ---------------------------------------------------------------------------
template <int FG, int ROWS, int PREV, bool IN32>
__global__ void k_spmvh(const int* __restrict__ rowPtr, const int* __restrict__ colS,
                        const float* __restrict__ valS,
                        const void* __restrict__ xin, const void* __restrict__ xprev,
                        uint4* __restrict__ y, int FGS) {
    int f = threadIdx.x;
    int v = blockIdx.x * ROWS + threadIdx.y;
    int s = rowPtr[v], e = rowPtr[v + 1];
    float acc[8];
#pragma unroll
    for (int j = 0; j < 8; j++) acc[j] = 0.f;

    const uint4* xh = (const uint4*)xin;
    const float4* x32 = (const float4*)xin;

    int i = s;
    for (; i + 4 <= e; i += 4) {
        int cc[4]; float ww[4];
#pragma unroll
        for (int t = 0; t < 4; t++) { cc[t] = colS[i + t]; ww[t] = valS[i + t]; }
        if (IN32) {
#pragma unroll
            for (int t = 0; t < 4; t++) {
                float4 a = x32[(size_t)cc[t] * FGS * 2 + 2 * f];
                float4 b = x32[(size_t)cc[t] * FGS * 2 + 2 * f + 1];
                acc[0] += ww[t] * a.x; acc[1] += ww[t] * a.y;
                acc[2] += ww[t] * a.z; acc[3] += ww[t] * a.w;
                acc[4] += ww[t] * b.x; acc[5] += ww[t] * b.y;
                acc[6] += ww[t] * b.z; acc[7] += ww[t] * b.w;
            }
        } else {
            uint4 u[4];
#pragma unroll
            for (int t = 0; t < 4; t++) u[t] = xh[(size_t)cc[t] * FGS + f];
#pragma unroll
            for (int t = 0; t < 4; t++) {
                float g[8]; h8_unpack(u[t], g);
#pragma unroll
                for (int j = 0; j < 8; j++) acc[j] += ww[t] * g[j];
            }
        }
    }
    for (; i < e; i++) {
        int c = colS[i]; float w = valS[i];
        if (IN32) {
            float4 a = x32[(size_t)c * FGS * 2 + 2 * f];
            float4 b = x32[(size_t)c * FGS * 2 + 2 * f + 1];
            acc[0] += w * a.x; acc[1] += w * a.y; acc[2] += w * a.z; acc[3] += w * a.w;
            acc[4] += w * b.x; acc[5] += w * b.y; acc[6] += w * b.z; acc[7] += w * b.w;
        } else {
            uint4 u = xh[(size_t)c * FGS + f];
            float g[8]; h8_unpack(u, g);
#pragma unroll
            for (int j = 0; j < 8; j++) acc[j] += w * g[j];
        }
    }

    if (PREV == 1) {
        const float4* p32 = (const float4*)xprev;
        float4 a = p32[(size_t)v * FGS * 2 + 2 * f];
        float4 b = p32[(size_t)v * FGS * 2 + 2 * f + 1];
        acc[0] = 2.f * acc[0] - a.x; acc[1] = 2.f * acc[1] - a.y;
        acc[2] = 2.f * acc[2] - a.z; acc[3] = 2.f * acc[3] - a.w;
        acc[4] = 2.f * acc[4] - b.x; acc[5] = 2.f * acc[5] - b.y;
        acc[6] = 2.f * acc[6] - b.z; acc[7] = 2.f * acc[7] - b.w;
    } else if (PREV == 2) {
        uint4 u = ((const uint4*)xprev)[(size_t)v * FGS + f];
        float g[8]; h8_unpack(u, g);
#pragma unroll
        for (int j = 0; j < 8; j++) acc[j] = 2.f * acc[j] - g[j];
    }
    y[(size_t)v * FGS + f] = h8_pack(acc);
}

// ---------------------------------------------------------------------------
// mma.sync bf16x3 Chebyshev GEMM, two-phase. Slot 0 = fp32 A0; slots 1..9 fp16.
// ---------------------------------------------------------------------------
__device__ __forceinline__ void mma16816(float* d, const uint32_t* a, const uint32_t* b) {
    asm volatile(
        "mma.sync.aligned.m16n8k16.row.col.f32.bf16.bf16.f32 "
        "{%0,%1,%2,%3}, {%4,%5,%6,%7}, {%8,%9}, {%0,%1,%2,%3};\n"
        : "+f"(d[0]), "+f"(d[1]), "+f"(d[2]), "+f"(d[3])
        : "r"(a[0]), "r"(a[1]), "r"(a[2]), "r"(a[3]), "r"(b[0]), "r"(b[1]));
}

__device__ __forceinline__ void split_pack2(float x0, float x1, uint32_t& hi, uint32_t& lo) {
    __nv_bfloat16 h0 = __float2bfloat16_rn(x0);
    __nv_bfloat16 h1 = __float2bfloat16_rn(x1);
    __nv_bfloat16 l0 = __float2bfloat16_rn(x0 - __bfloat162float(h0));
    __nv_bfloat16 l1 = __float2bfloat16_rn(x1 - __bfloat162float(h1));
    __nv_bfloat162 hv(h0, h1), lv(l0, l1);
    hi = *(uint32_t*)&hv;
    lo = *(uint32_t*)&lv;
}

template <int CIN, int COUT, int PHASE>
__global__ __launch_bounds__(256)
void k_gemm_mma(const float* __restrict__ A0, const __half* __restrict__ ArestH,
                size_t slotStride, const float* __restrict__ W,
                const float* __restrict__ bias,
                float* __restrict__ partial, float* __restrict__ out,
                int c0, int c1) {
    constexpr int NT = COUT / 8;

    __shared__ uint32_t Ah[128][17];
    __shared__ uint32_t Al[128][17];
    __shared__ uint32_t Bh[COUT][17];
    __shared__ uint32_t Bl[COUT][17];

    int tid = threadIdx.x;
    int lane = tid & 31;
    int w = tid >> 5;
    int mBase = blockIdx.x * 128;

    float acc[NT][4];
#pragma unroll
    for (int j = 0; j < NT; j++)
#pragma unroll
        for (int q = 0; q < 4; q++) acc[j][q] = 0.f;

    for (int c = c0; c < c1; c++) {
#pragma unroll
        for (int it = 0; it < 4; it++) {
            int idx = it * 256 + tid;
            int r = idx >> 3;
            int q = idx & 7;
            int kk = c * 32 + q * 4;
            int s = kk / CIN;
            int off = kk % CIN;
            uint32_t h0, l0, h1, l1;
            if (s == 0) {
                float4 a = *(const float4*)(A0 + (size_t)(mBase + r) * CIN + off);
                split_pack2(a.x, a.y, h0, l0);
                split_pack2(a.z, a.w, h1, l1);
            } else {
                const __half* src = ArestH + (size_t)(s - 1) * slotStride
                                    + (size_t)(mBase + r) * CIN + off;
                uint2 u = *(const uint2*)src;
                float2 fa = __half22float2(*(__half2*)&u.x);
                float2 fb = __half22float2(*(__half2*)&u.y);
                split_pack2(fa.x, fa.y, h0, l0);
                split_pack2(fb.x, fb.y, h1, l1);
            }
            Ah[r][2 * q] = h0; Ah[r][2 * q + 1] = h1;
            Al[r][2 * q] = l0; Al[r][2 * q + 1] = l1;
        }
        for (int idx = tid; idx < COUT * 16; idx += 256) {
            int k2 = idx / COUT;
            int n = idx % COUT;
            int kk = c * 32 + 2 * k2;
            int s = kk / CIN;
            int off = kk % CIN;
            const float* wp = W + ((size_t)s * CIN + off) * COUT + n;
            float w0 = __ldg(wp);
            float w1 = __ldg(wp + COUT);
            uint32_t h, l;
            split_pack2(w0, w1, h, l);
            Bh[n][k2] = h;
            Bl[n][k2] = l;
        }
        __syncthreads();

#pragma unroll
        for (int ks = 0; ks < 2; ks++) {
            int kq = ks * 8 + (lane & 3);
            int r0 = w * 16 + (lane >> 2);
            uint32_t ah[4], al[4];
            ah[0] = Ah[r0][kq];     ah[1] = Ah[r0 + 8][kq];
            ah[2] = Ah[r0][kq + 4]; ah[3] = Ah[r0 + 8][kq + 4];
            al[0] = Al[r0][kq];     al[1] = Al[r0 + 8][kq];
            al[2] = Al[r0][kq + 4]; al[3] = Al[r0 + 8][kq + 4];
#pragma unroll
            for (int j = 0; j < NT; j++) {
                int n = j * 8 + (lane >> 2);
                uint32_t bh[2] = { Bh[n][kq], Bh[n][kq + 4] };
                uint32_t bl[2] = { Bl[n][kq], Bl[n][kq + 4] };
                mma16816(acc[j], ah, bh);
                mma16816(acc[j], al, bh);
                mma16816(acc[j], ah, bl);
            }
        }
        __syncthreads();
    }

    int r0 = mBase + w * 16 + (lane >> 2);
#pragma unroll
    for (int j = 0; j < NT; j++) {
        int n = j * 8 + 2 * (lane & 3);
        if (PHASE == 0) {
            *(float2*)&partial[(size_t)r0 * COUT + n] = make_float2(acc[j][0], acc[j][1]);
            *(float2*)&partial[(size_t)(r0 + 8) * COUT + n] = make_float2(acc[j][2], acc[j][3]);
        } else {
            float2 q0 = *(const float2*)&partial[(size_t)r0 * COUT + n];
            float2 q1 = *(const float2*)&partial[(size_t)(r0 + 8) * COUT + n];
            float b0 = __ldg(&bias[n]);
            float b1 = __ldg(&bias[n + 1]);
            float2 o0 = make_float2(elu1(acc[j][0] + q0.x + b0), elu1(acc[j][1] + q0.y + b1));
            float2 o1 = make_float2(elu1(acc[j][2] + q1.x + b0), elu1(acc[j][3] + q1.y + b1));
            *(float2*)&out[(size_t)r0 * COUT + n] = o0;
            *(float2*)&out[(size_t)(r0 + 8) * COUT + n] = o1;
        }
    }
}

// CIN=1 special case (level-1 conv1); slots fp16
__global__ void k_gemm_c1(const float* __restrict__ A0, const __half* __restrict__ ArestH,
                          size_t slotStride, const float* __restrict__ W,
                          const float* __restrict__ bias, float* __restrict__ out, int M) {
    __shared__ float Ws[10][32];
    __shared__ float bs[32];
    int tid = threadIdx.y * 32 + threadIdx.x;
    for (int t = tid; t < 320; t += 256) Ws[t / 32][t % 32] = W[t];
    if (tid < 32) bs[tid] = bias[tid];
    __syncthreads();
    int m = blockIdx.x * 8 + threadIdx.y;
    int n = threadIdx.x;
    float acc = A0[m] * Ws[0][n];
#pragma unroll
    for (int k = 1; k < 10; k++)
        acc += __half2float(ArestH[(size_t)(k - 1) * slotStride + m]) * Ws[k][n];
    out[(size_t)m * 32 + n] = elu1(acc + bs[n]);
}

// ---------------------------------------------------------------------------
// Fused skip-write + pooling
// ---------------------------------------------------------------------------
__global__ void k_skip_pool_next4(const float4* __restrict__ in, float4* __restrict__ skip,
                                  float4* __restrict__ pool, int Vin, int C4) {
    int t = blockIdx.x * blockDim.x + threadIdx.x;
    int F4 = BATCH * C4;
    int n = (Vin / 4) * F4;
    if (t >= n) return;
    int v4 = t / F4;
    int f = t - v4 * F4;
    int b = f / C4;
    int c = f - b * C4;
    const float4* bp = in + (size_t)(4 * v4) * F4 + f;
    float4 a0 = bp[0], a1 = bp[F4], a2 = bp[2 * F4], a3 = bp[3 * F4];
    skip[((size_t)b * Vin + 4 * v4 + 0) * C4 + c] = a0;
    skip[((size_t)b * Vin + 4 * v4 + 1) * C4 + c] = a1;
    skip[((size_t)b * Vin + 4 * v4 + 2) * C4 + c] = a2;
    skip[((size_t)b * Vin + 4 * v4 + 3) * C4 + c] = a3;
    float4 o;
    o.x = 0.25f * (a0.x + a1.x + a2.x + a3.x);
    o.y = 0.25f * (a0.y + a1.y + a2.y + a3.y);
    o.z = 0.25f * (a0.z + a1.z + a2.z + a3.z);
    o.w = 0.25f * (a0.w + a1.w + a2.w + a3.w);
    pool[t] = o;
}
__global__ void k_skip_pool_out4(const float4* __restrict__ in, float4* __restrict__ skip,
                                 float4* __restrict__ poolT, int Vin, int C4) {
    int t = blockIdx.x * blockDim.x + threadIdx.x;
    int F4 = BATCH * C4;
    int Vout = Vin / 4;
    int n = Vout * F4;
    if (t >= n) return;
    int v4 = t / F4;
    int f = t - v4 * F4;
    int b = f / C4;
    int c = f - b * C4;
    const float4* bp = in + (size_t)(4 * v4) * F4 + f;
    float4 a0 = bp[0], a1 = bp[F4], a2 = bp[2 * F4], a3 = bp[3 * F4];
    skip[((size_t)b * Vin + 4 * v4 + 0) * C4 + c] = a0;
    skip[((size_t)b * Vin + 4 * v4 + 1) * C4 + c] = a1;
    skip[((size_t)b * Vin + 4 * v4 + 2) * C4 + c] = a2;
    skip[((size_t)b * Vin + 4 * v4 + 3) * C4 + c] = a3;
    float4 o;
    o.x = 0.25f * (a0.x + a1.x + a2.x + a3.x);
    o.y = 0.25f * (a0.y + a1.y + a2.y + a3.y);
    o.z = 0.25f * (a0.z + a1.z + a2.z + a3.z);
    o.w = 0.25f * (a0.w + a1.w + a2.w + a3.w);
    poolT[((size_t)b * Vout + v4) * C4 + c] = o;
}

// ---------------------------------------------------------------------------
// Host orchestration
// ---------------------------------------------------------------------------
static inline int divUp(int a, int b) { return (a + b - 1) / b; }

struct Csr { int* rowPtr; int* cursor; int* colS; float* valS; int* orig; int* bsum; };

struct DevPtrs {
    float* cheb; float* b0; float* b1; float* b2;
    Csr c1, c2, c3;
};
static void get_ptrs(DevPtrs& p) {
    cudaGetSymbolAddress((void**)&p.cheb, g_cheb);
    cudaGetSymbolAddress((void**)&p.b0, g_out);
    cudaGetSymbolAddress((void**)&p.b1, g_out2);
    cudaGetSymbolAddress((void**)&p.b2, g_part);
    cudaGetSymbolAddress((void**)&p.c1.rowPtr, g_rowPtr1);
    cudaGetSymbolAddress((void**)&p.c1.cursor, g_cursor1);
    cudaGetSymbolAddress((void**)&p.c1.colS, g_colS1);
    cudaGetSymbolAddress((void**)&p.c1.valS, g_valS1);
    cudaGetSymbolAddress((void**)&p.c1.orig, g_orig1);
    cudaGetSymbolAddress((void**)&p.c1.bsum, g_bsum1);
    cudaGetSymbolAddress((void**)&p.c2.rowPtr, g_rowPtr2);
    cudaGetSymbolAddress((void**)&p.c2.cursor, g_cursor2);
    cudaGetSymbolAddress((void**)&p.c2.colS, g_colS2);
    cudaGetSymbolAddress((void**)&p.c2.valS, g_valS2);
    cudaGetSymbolAddress((void**)&p.c2.orig, g_orig2);
    cudaGetSymbolAddress((void**)&p.c2.bsum, g_bsum2);
    cudaGetSymbolAddress((void**)&p.c3.rowPtr, g_rowPtr3);
    cudaGetSymbolAddress((void**)&p.c3.cursor, g_cursor3);
    cudaGetSymbolAddress((void**)&p.c3.colS, g_colS3);
    cudaGetSymbolAddress((void**)&p.c3.valS, g_valS3);
    cudaGetSymbolAddress((void**)&p.c3.orig, g_orig3);
    cudaGetSymbolAddress((void**)&p.c3.bsum, g_bsum3);
}

static void build_csr(const Csr& c, const int* rows, const int* cols, const float* vals,
                      int V, int E, cudaStream_t st) {
    k_zero_int<<<divUp(V + 1, 256), 256, 0, st>>>(c.cursor, V + 1);
    k_hist<<<divUp(E, 256), 256, 0, st>>>(rows, c.cursor, E);
    int nb = divUp(V, 1024);
    k_scan_block<<<nb, 1024, 0, st>>>(c.cursor, c.rowPtr, c.bsum, V);
    k_scan_top<<<1, 64, 0, st>>>(c.bsum, nb);
    k_scan_add<<<divUp(V + 1, 256), 256, 0, st>>>(c.rowPtr, c.cursor, c.bsum, V, E);
    k_scatter<<<divUp(E, 256), 256, 0, st>>>(rows, cols, vals, c.cursor, c.colS, c.valS, c.orig, E);
    k_rowsort<<<divUp(V, 256), 256, 0, st>>>(c.rowPtr, c.colS, c.valS, c.orig, V);
}

// fp16 Chebyshev chain. Slots 1..9 at (half*)cheb + (k-1)*V*FTOT.
template <int F, int FTOT>
static void spmv_chainh(const DevPtrs& p, const Csr& c, const float* x0base, int V,
                        int f8off, cudaStream_t st, cudaEvent_t evMid = nullptr) {
    constexpr int FG = F / 8;
    constexpr int ROWS = (FG >= 256) ? 1 : (256 / FG);
    constexpr int FGS = FTOT / 8;
    dim3 blk(FG, ROWS);
    size_t S = (size_t)V * FTOT;   // halves per slot
    __half* h = (__half*)p.cheb;
    const void* x0 = (const void*)((const float4*)x0base + f8off * 2);
    auto slot = [&](int k) { return (uint4*)(h + (size_t)(k - 1) * S) + f8off; };

    k_spmvh<FG, ROWS, 0, true><<<V / ROWS, blk, 0, st>>>(
        c.rowPtr, c.colS, c.valS, x0, nullptr, slot(1), FGS);
    k_spmvh<FG, ROWS, 1, false><<<V / ROWS, blk, 0, st>>>(
        c.rowPtr, c.colS, c.valS, slot(1), x0, slot(2), FGS);
    for (int k = 3; k < 10; k++) {
        k_spmvh<FG, ROWS, 2, false><<<V / ROWS, blk, 0, st>>>(
            c.rowPtr, c.colS, c.valS, slot(k - 1), slot(k - 2), slot(k), FGS);
        if (evMid && k == 4) cudaEventRecord(evMid, st);
    }
}

extern "C" void kernel_launch(void* const* d_in, const int* in_sizes, int n_in,
                              void* d_out_v, int out_size) {
    (void)in_sizes; (void)n_in; (void)out_size;
    DevPtrs p; get_ptrs(p);
    const __half* hs = (const __half*)p.cheb;

    static cudaStream_t s0 = nullptr, s1 = nullptr;
    static cudaEvent_t evRoot, evT, evC2, evC3, evEnd;
    static cudaEvent_t evMid[5], evP1[5];
    if (!s0) {
        cudaStreamCreateWithFlags(&s0, cudaStreamNonBlocking);
        cudaStreamCreateWithFlags(&s1, cudaStreamNonBlocking);
        cudaEventCreateWithFlags(&evRoot, cudaEventDisableTiming);
        cudaEventCreateWithFlags(&evT, cudaEventDisableTiming);
        cudaEventCreateWithFlags(&evC2, cudaEventDisableTiming);
        cudaEventCreateWithFlags(&evC3, cudaEventDisableTiming);
        cudaEventCreateWithFlags(&evEnd, cudaEventDisableTiming);
        for (int i = 0; i < 5; i++) {
            cudaEventCreateWithFlags(&evMid[i], cudaEventDisableTiming);
            cudaEventCreateWithFlags(&evP1[i], cudaEventDisableTiming);
        }
    }

    const float* x    = (const float*)d_in[0];
    const float* w1_1 = (const float*)d_in[1];
    const float* b1_1 = (const float*)d_in[2];
    const float* w2_1 = (const float*)d_in[3];
    const float* b2_1 = (const float*)d_in[4];
    const int*   rows1 = (const int*)d_in[5];
    const int*   cols1 = (const int*)d_in[6];
    const float* vals1 = (const float*)d_in[7];
    const float* w1_2 = (const float*)d_in[8];
    const float* b1_2 = (const float*)d_in[9];
    const float* w2_2 = (const float*)d_in[10];
    const float* b2_2 = (const float*)d_in[11];
    const int*   rows2 = (const int*)d_in[12];
    const int*   cols2 = (const int*)d_in[13];
    const float* vals2 = (const float*)d_in[14];
    const float* w1_3 = (const float*)d_in[15];
    const float* b1_3 = (const float*)d_in[16];
    const float* w2_3 = (const float*)d_in[17];
    const float* b2_3 = (const float*)d_in[18];
    const int*   rows3 = (const int*)d_in[19];
    const int*   cols3 = (const int*)d_in[20];
    const float* vals3 = (const float*)d_in[21];

    float* d_out = (float*)d_out_v;
    float* out_skip1 = d_out;                       // [8,49152,32]
    float* out_skip2 = d_out + (size_t)12582912;    // [8,12288,64]
    float* out_skip3 = out_skip2 + (size_t)6291456; // [8,3072,128]
    float* out_x     = out_skip3 + (size_t)3145728; // [8,768,128]

    // ---- fork ----
    cudaEventRecord(evRoot, 0);
    cudaStreamWaitEvent(s0, evRoot, 0);
    cudaStreamWaitEvent(s1, evRoot, 0);

    // s1: transpose x -> b0; CSR builds for levels 2/3 hidden behind level-1
    k_transpose_in<<<divUp(V1, 256), 256, 0, s1>>>(x, p.b0, V1);
    cudaEventRecord(evT, s1);
    build_csr(p.c2, rows2, cols2, vals2, V2, E2, s1);
    cudaEventRecord(evC2, s1);
    build_csr(p.c3, rows3, cols3, vals3, V3, E3, s1);
    cudaEventRecord(evC3, s1);

    // s0: level-1 CSR, F=8 chain, conv1 GEMM (A0=b0 -> b1)
    build_csr(p.c1, rows1, cols1, vals1, V1, E1, s0);
    cudaStreamWaitEvent(s0, evT, 0);
    spmv_chainh<8, 8>(p, p.c1, p.b0, V1, 0, s0);
    k_gemm_c1<<<V1 * BATCH / 8, dim3(32, 8), 0, s0>>>(
        p.b0, hs, (size_t)V1 * 8, w1_1, b1_1, p.b1, V1 * BATCH);

    // level-1 conv2: serial half-chains (x0=b1), evMid after half-B slot 4
    spmv_chainh<128, 256>(p, p.c1, p.b1, V1, 0, s0);
    spmv_chainh<128, 256>(p, p.c1, p.b1, V1, 16, s0, evMid[0]);
    cudaStreamWaitEvent(s1, evMid[0], 0);
    k_gemm_mma<32, 32, 0><<<V1 * BATCH / 128, 256, 0, s1>>>(
        p.b1, hs, (size_t)V1 * 256, w2_1, b2_1, p.b2, nullptr, 0, 5);
    cudaEventRecord(evP1[0], s1);
    cudaStreamWaitEvent(s0, evP1[0], 0);
    k_gemm_mma<32, 32, 1><<<V1 * BATCH / 128, 256, 0, s0>>>(
        p.b1, hs, (size_t)V1 * 256, w2_1, b2_1, p.b2, p.b0, 5, 10);
    {
        int n2 = (V1 / 4) * BATCH * 8;
        k_skip_pool_next4<<<divUp(n2, 256), 256, 0, s0>>>(
            (const float4*)p.b0, (float4*)out_skip1, (float4*)p.b1, V1, 8);
    }

    // ---------------- Level 2 ----------------
    cudaStreamWaitEvent(s0, evC2, 0);
    spmv_chainh<256, 256>(p, p.c2, p.b1, V2, 0, s0, evMid[1]);
    cudaStreamWaitEvent(s1, evMid[1], 0);
    k_gemm_mma<32, 64, 0><<<V2 * BATCH / 128, 256, 0, s1>>>(
        p.b1, hs, (size_t)V2 * 256, w1_2, b1_2, p.b2, nullptr, 0, 5);
    cudaEventRecord(evP1[1], s1);
    cudaStreamWaitEvent(s0, evP1[1], 0);
    k_gemm_mma<32, 64, 1><<<V2 * BATCH / 128, 256, 0, s0>>>(
        p.b1, hs, (size_t)V2 * 256, w1_2, b1_2, p.b2, p.b0, 5, 10);

    spmv_chainh<512, 512>(p, p.c2, p.b0, V2, 0, s0, evMid[2]);
    cudaStreamWaitEvent(s1, evMid[2], 0);
    k_gemm_mma<64, 64, 0><<<V2 * BATCH / 128, 256, 0, s1>>>(
        p.b0, hs, (size_t)V2 * 512, w2_2, b2_2, p.b2, nullptr, 0, 10);
    cudaEventRecord(evP1[2], s1);
    cudaStreamWaitEvent(s0, evP1[2], 0);
    k_gemm_mma<64, 64, 1><<<V2 * BATCH / 128, 256, 0, s0>>>(
        p.b0, hs, (size_t)V2 * 512, w2_2, b2_2, p.b2, p.b1, 10, 20);
    {
        int n2 = (V2 / 4) * BATCH * 16;
        k_skip_pool_next4<<<divUp(n2, 256), 256, 0, s0>>>(
            (const float4*)p.b1, (float4*)out_skip2, (float4*)p.b0, V2, 16);
    }

    // ---------------- Level 3 ----------------
    cudaStreamWaitEvent(s0, evC3, 0);
    spmv_chainh<512, 512>(p, p.c3, p.b0, V3, 0, s0, evMid[3]);
    cudaStreamWaitEvent(s1, evMid[3], 0);
    k_gemm_mma<64, 128, 0><<<V3 * BATCH / 128, 256, 0, s1>>>(
        p.b0, hs, (size_t)V3 * 512, w1_3, b1_3, p.b2, nullptr, 0, 10);
    cudaEventRecord(evP1[3], s1);
    cudaStreamWaitEvent(s0, evP1[3], 0);
    k_gemm_mma<64, 128, 1><<<V3 * BATCH / 128, 256, 0, s0>>>(
        p.b0, hs, (size_t)V3 * 512, w1_3, b1_3, p.b2, p.b1, 10, 20);

    spmv_chainh<1024, 1024>(p, p.c3, p.b1, V3, 0, s0, evMid[4]);
    cudaStreamWaitEvent(s1, evMid[4], 0);
    k_gemm_mma<128, 128, 0><<<V3 * BATCH / 128, 256, 0, s1>>>(
        p.b1, hs, (size_t)V3 * 1024, w2_3, b2_3, p.b2, nullptr, 0, 20);
    cudaEventRecord(evP1[4], s1);
    cudaStreamWaitEvent(s0, evP1[4], 0);
    k_gemm_mma<128, 128, 1><<<V3 * BATCH / 128, 256, 0, s0>>>(
        p.b1, hs, (size_t)V3 * 1024, w2_3, b2_3, p.b2, p.b0, 20, 40);
    {
        int n2 = (V3 / 4) * BATCH * 32;
        k_skip_pool_out4<<<divUp(n2, 256), 256, 0, s0>>>(
            (const float4*)p.b0, (float4*)out_skip3, (float4*)out_x, V3, 32);
    }

    // ---- join ----
    cudaEventRecord(evEnd, s0);
    cudaStreamWaitEvent(0, evEnd, 0);
}